// round 1
// baseline (speedup 1.0000x reference)
#include <cuda_runtime.h>

#define Dv 128
#define Hv 128
#define Wv 128
#define VOX (Dv*Hv*Wv)
#define NSL 16
#define NPIX (NSL*128*128)
#define NIT 10

// Scratch (device globals: no runtime allocation allowed)
__device__ float g_b[VOX];
__device__ float g_x[VOX];
__device__ float g_r[VOX];
__device__ float g_p[VOX];
__device__ float g_Ap[VOX];
__device__ double g_rr[NIT + 1];
__device__ double g_pAp[NIT];

// ---------------------------------------------------------------------------
// Trilinear gather with OOB-zero semantics (matches reference _corners)
// ---------------------------------------------------------------------------
__device__ __forceinline__ float trigather(const float* __restrict__ vol,
                                           float px, float py, float pz) {
    if (px <= -1.f || py <= -1.f || pz <= -1.f ||
        px >= (float)Wv || py >= (float)Hv || pz >= (float)Dv) return 0.f;
    float xf = floorf(px), yf = floorf(py), zf = floorf(pz);
    int ix = (int)xf, iy = (int)yf, iz = (int)zf;
    float fx = px - xf, fy = py - yf, fz = pz - zf;
    float gx = 1.f - fx, gy = 1.f - fy, gz = 1.f - fz;
    if (ix >= 0 && ix < Wv - 1 && iy >= 0 && iy < Hv - 1 && iz >= 0 && iz < Dv - 1) {
        const float* q = vol + (iz * Hv + iy) * Wv + ix;
        float v000 = __ldg(q),        v001 = __ldg(q + 1);
        float v010 = __ldg(q + Wv),   v011 = __ldg(q + Wv + 1);
        const float* q2 = q + Hv * Wv;
        float v100 = __ldg(q2),       v101 = __ldg(q2 + 1);
        float v110 = __ldg(q2 + Wv),  v111 = __ldg(q2 + Wv + 1);
        float s0 = (v000 * gx + v001 * fx) * gy + (v010 * gx + v011 * fx) * fy;
        float s1 = (v100 * gx + v101 * fx) * gy + (v110 * gx + v111 * fx) * fy;
        return s0 * gz + s1 * fz;
    }
    float s = 0.f;
    #pragma unroll
    for (int dz = 0; dz < 2; dz++)
    #pragma unroll
    for (int dy = 0; dy < 2; dy++)
    #pragma unroll
    for (int dx = 0; dx < 2; dx++) {
        int xi = ix + dx, yi = iy + dy, zi = iz + dz;
        if ((unsigned)xi < (unsigned)Wv && (unsigned)yi < (unsigned)Hv &&
            (unsigned)zi < (unsigned)Dv) {
            float wt = (dx ? fx : gx) * (dy ? fy : gy) * (dz ? fz : gz);
            s += wt * __ldg(vol + (zi * Hv + yi) * Wv + xi);
        }
    }
    return s;
}

// ---------------------------------------------------------------------------
// Trilinear scatter-add (exact transpose of gather)
// ---------------------------------------------------------------------------
__device__ __forceinline__ void triscatter(float* __restrict__ vol,
                                           float px, float py, float pz, float val) {
    if (px <= -1.f || py <= -1.f || pz <= -1.f ||
        px >= (float)Wv || py >= (float)Hv || pz >= (float)Dv) return;
    float xf = floorf(px), yf = floorf(py), zf = floorf(pz);
    int ix = (int)xf, iy = (int)yf, iz = (int)zf;
    float fx = px - xf, fy = py - yf, fz = pz - zf;
    float gx = 1.f - fx, gy = 1.f - fy, gz = 1.f - fz;
    if (ix >= 0 && ix < Wv - 1 && iy >= 0 && iy < Hv - 1 && iz >= 0 && iz < Dv - 1) {
        float* q = vol + (iz * Hv + iy) * Wv + ix;
        float w0 = val * gz, w1 = val * fz;
        atomicAdd(q,           gx * gy * w0);
        atomicAdd(q + 1,       fx * gy * w0);
        atomicAdd(q + Wv,      gx * fy * w0);
        atomicAdd(q + Wv + 1,  fx * fy * w0);
        float* q2 = q + Hv * Wv;
        atomicAdd(q2,          gx * gy * w1);
        atomicAdd(q2 + 1,      fx * gy * w1);
        atomicAdd(q2 + Wv,     gx * fy * w1);
        atomicAdd(q2 + Wv + 1, fx * fy * w1);
    } else {
        #pragma unroll
        for (int dz = 0; dz < 2; dz++)
        #pragma unroll
        for (int dy = 0; dy < 2; dy++)
        #pragma unroll
        for (int dx = 0; dx < 2; dx++) {
            int xi = ix + dx, yi = iy + dy, zi = iz + dz;
            if ((unsigned)xi < (unsigned)Wv && (unsigned)yi < (unsigned)Hv &&
                (unsigned)zi < (unsigned)Dv) {
                float wt = (dx ? fx : gx) * (dy ? fy : gy) * (dz ? fz : gz);
                atomicAdd(vol + (zi * Hv + yi) * Wv + xi, wt * val);
            }
        }
    }
}

// ---------------------------------------------------------------------------
// Fused apply kernel. GATHER=true: vout += AtA(vin). GATHER=false: vout += At(src).
// One thread per slice pixel; 27 PSF samples each.
// ---------------------------------------------------------------------------
template <bool GATHER>
__global__ void __launch_bounds__(256) apply_kernel(
    const float* __restrict__ theta, const float* __restrict__ psf,
    const float* __restrict__ vin, const float* __restrict__ src,
    float* __restrict__ vout)
{
    int tid = blockIdx.x * 256 + threadIdx.x;   // = n*16384 + h*128 + w
    int n = tid >> 14;
    int h = (tid >> 7) & 127;
    int w = tid & 127;
    const float* T = theta + n * 12;
    float R00 = __ldg(T + 0), R01 = __ldg(T + 1),  R02 = __ldg(T + 2),  t0 = __ldg(T + 3);
    float R10 = __ldg(T + 4), R11 = __ldg(T + 5),  R12 = __ldg(T + 6),  t1 = __ldg(T + 7);
    float R20 = __ldg(T + 8), R21 = __ldg(T + 9),  R22 = __ldg(T + 10), t2 = __ldg(T + 11);
    float u = ((float)w - 63.5f) * 1.5f;
    float v = ((float)h - 63.5f) * 1.5f;
    float cx = R00 * u + R01 * v + t0 + 63.5f;
    float cy = R10 * u + R11 * v + t1 + 63.5f;
    float cz = R20 * u + R21 * v + t2 + 63.5f;

    float s;
    if (GATHER) {
        s = 0.f;
        #pragma unroll 1
        for (int k = 0; k < 27; k++) {
            float ox = (float)(k % 3 - 1);
            float oy = (float)((k / 3) % 3 - 1);
            float oz = (float)(k / 9 - 1);
            float px = cx + ox * R00 + oy * R01 + oz * R02;
            float py = cy + ox * R10 + oy * R11 + oz * R12;
            float pz = cz + ox * R20 + oy * R21 + oz * R22;
            s += __ldg(psf + k) * trigather(vin, px, py, pz);
        }
    } else {
        s = __ldg(src + tid);
    }
    if (s != 0.f) {
        #pragma unroll 1
        for (int k = 0; k < 27; k++) {
            float ox = (float)(k % 3 - 1);
            float oy = (float)((k / 3) % 3 - 1);
            float oz = (float)(k / 9 - 1);
            float px = cx + ox * R00 + oy * R01 + oz * R02;
            float py = cy + ox * R10 + oy * R11 + oz * R12;
            float pz = cz + ox * R20 + oy * R21 + oz * R22;
            triscatter(vout, px, py, pz, __ldg(psf + k) * s);
        }
    }
}

// ---------------------------------------------------------------------------
// CG plumbing
// ---------------------------------------------------------------------------
__device__ __forceinline__ void block_reduce_add(double v, double* dst) {
    #pragma unroll
    for (int o = 16; o; o >>= 1) v += __shfl_down_sync(0xffffffffu, v, o);
    __shared__ double sh[8];
    int lane = threadIdx.x & 31, wid = threadIdx.x >> 5;
    if (lane == 0) sh[wid] = v;
    __syncthreads();
    if (wid == 0) {
        v = (lane < 8) ? sh[lane] : 0.0;
        #pragma unroll
        for (int o = 4; o; o >>= 1) v += __shfl_down_sync(0xffffffffu, v, o);
        if (lane == 0) atomicAdd(dst, v);
    }
}

__global__ void __launch_bounds__(256) zero_init_kernel() {
    int i = blockIdx.x * 256 + threadIdx.x;
    g_b[i] = 0.f;
    g_Ap[i] = 0.f;
    if (blockIdx.x == 0) {
        if (threadIdx.x < NIT + 1) g_rr[threadIdx.x] = 0.0;
        if (threadIdx.x >= 32 && threadIdx.x < 32 + NIT) g_pAp[threadIdx.x - 32] = 0.0;
    }
}

__global__ void __launch_bounds__(256) copy_x_kernel(const float* __restrict__ vol) {
    int i = blockIdx.x * 256 + threadIdx.x;
    g_x[i] = vol[i];
}

__global__ void __launch_bounds__(256) zero_Ap_kernel() {
    int i = blockIdx.x * 256 + threadIdx.x;
    g_Ap[i] = 0.f;
}

__global__ void __launch_bounds__(256) init_r_kernel() {
    int i = blockIdx.x * 256 + threadIdx.x;
    float rv = g_b[i] - g_Ap[i];
    g_r[i] = rv;
    g_p[i] = rv;
    block_reduce_add((double)rv * (double)rv, &g_rr[0]);
}

__global__ void __launch_bounds__(256) dot_pAp_kernel(int it) {
    int i = blockIdx.x * 256 + threadIdx.x;
    block_reduce_add((double)g_p[i] * (double)g_Ap[i], &g_pAp[it]);
}

__global__ void __launch_bounds__(256) update_xr_kernel(int it) {
    __shared__ float s_alpha;
    if (threadIdx.x == 0) s_alpha = (float)(g_rr[it] / g_pAp[it]);
    __syncthreads();
    float alpha = s_alpha;
    int i = blockIdx.x * 256 + threadIdx.x;
    g_x[i] = g_x[i] + alpha * g_p[i];
    float rv = g_r[i] - alpha * g_Ap[i];
    g_r[i] = rv;
    block_reduce_add((double)rv * (double)rv, &g_rr[it + 1]);
}

__global__ void __launch_bounds__(256) update_p_kernel(int it) {
    __shared__ float s_beta;
    if (threadIdx.x == 0) s_beta = (float)(g_rr[it + 1] / g_rr[it]);
    __syncthreads();
    float beta = s_beta;
    int i = blockIdx.x * 256 + threadIdx.x;
    g_p[i] = g_r[i] + beta * g_p[i];
}

__global__ void __launch_bounds__(256) relu_kernel(float* __restrict__ out) {
    int i = blockIdx.x * 256 + threadIdx.x;
    out[i] = fmaxf(g_x[i], 0.f);
}

// ---------------------------------------------------------------------------
// Launch
// ---------------------------------------------------------------------------
extern "C" void kernel_launch(void* const* d_in, const int* in_sizes, int n_in,
                              void* d_out, int out_size) {
    const float *theta = nullptr, *slices = nullptr, *volume = nullptr, *psf = nullptr;
    for (int i = 0; i < n_in; i++) {
        switch (in_sizes[i]) {
            case 192:     theta  = (const float*)d_in[i]; break;
            case 262144:  slices = (const float*)d_in[i]; break;
            case 2097152: volume = (const float*)d_in[i]; break;
            case 27:      psf    = (const float*)d_in[i]; break;
        }
    }
    float* out = (float*)d_out;

    static float* pb  = nullptr;
    static float* pp  = nullptr;
    static float* px_ = nullptr;
    static float* pAp = nullptr;
    if (!pb) {
        cudaGetSymbolAddress((void**)&pb,  g_b);
        cudaGetSymbolAddress((void**)&pp,  g_p);
        cudaGetSymbolAddress((void**)&px_, g_x);
        cudaGetSymbolAddress((void**)&pAp, g_Ap);
    }

    const int VB = VOX / 256;    // 8192 blocks
    const int PB = NPIX / 256;   // 1024 blocks

    zero_init_kernel<<<VB, 256>>>();
    copy_x_kernel<<<VB, 256>>>(volume);
    // b = At(slices)
    apply_kernel<false><<<PB, 256>>>(theta, psf, nullptr, slices, pb);
    // Ap = AtA(x0)
    apply_kernel<true><<<PB, 256>>>(theta, psf, px_, nullptr, pAp);
    // r = b - Ap; p = r; rr0 = r.r
    init_r_kernel<<<VB, 256>>>();

    for (int it = 0; it < NIT; it++) {
        zero_Ap_kernel<<<VB, 256>>>();
        apply_kernel<true><<<PB, 256>>>(theta, psf, pp, nullptr, pAp);
        dot_pAp_kernel<<<VB, 256>>>(it);
        update_xr_kernel<<<VB, 256>>>(it);
        update_p_kernel<<<VB, 256>>>(it);
    }
    relu_kernel<<<VB, 256>>>(out);
}

// round 2
// speedup vs baseline: 1.3228x; 1.3228x over previous
#include <cuda_runtime.h>

#define Dv 128
#define Hv 128
#define Wv 128
#define VOX (Dv*Hv*Wv)
#define NSL 16
#define NPIX (NSL*128*128)
#define NIT 10

// Scratch (device globals: no runtime allocation allowed)
__device__ float g_b[VOX];
__device__ float g_x[VOX];
__device__ float g_r[VOX];
__device__ float g_p[VOX];
__device__ float g_Ap[VOX];
__device__ double g_rr[NIT + 1];
__device__ double g_pAp[NIT];

// ---------------------------------------------------------------------------
// Guarded trilinear gather (general path, matches reference _corners exactly)
// ---------------------------------------------------------------------------
__device__ __forceinline__ float trigather_safe(const float* __restrict__ vol,
                                                float px, float py, float pz) {
    if (px <= -1.f || py <= -1.f || pz <= -1.f ||
        px >= (float)Wv || py >= (float)Hv || pz >= (float)Dv) return 0.f;
    float xf = floorf(px), yf = floorf(py), zf = floorf(pz);
    int ix = (int)xf, iy = (int)yf, iz = (int)zf;
    float fx = px - xf, fy = py - yf, fz = pz - zf;
    float gx = 1.f - fx, gy = 1.f - fy, gz = 1.f - fz;
    float s = 0.f;
    #pragma unroll
    for (int dz = 0; dz < 2; dz++)
    #pragma unroll
    for (int dy = 0; dy < 2; dy++)
    #pragma unroll
    for (int dx = 0; dx < 2; dx++) {
        int xi = ix + dx, yi = iy + dy, zi = iz + dz;
        if ((unsigned)xi < (unsigned)Wv && (unsigned)yi < (unsigned)Hv &&
            (unsigned)zi < (unsigned)Dv) {
            float wt = (dx ? fx : gx) * (dy ? fy : gy) * (dz ? fz : gz);
            s += wt * __ldg(vol + (zi * Hv + yi) * Wv + xi);
        }
    }
    return s;
}

__device__ __forceinline__ void triscatter_safe(float* __restrict__ vol,
                                                float px, float py, float pz, float val) {
    if (px <= -1.f || py <= -1.f || pz <= -1.f ||
        px >= (float)Wv || py >= (float)Hv || pz >= (float)Dv) return;
    float xf = floorf(px), yf = floorf(py), zf = floorf(pz);
    int ix = (int)xf, iy = (int)yf, iz = (int)zf;
    float fx = px - xf, fy = py - yf, fz = pz - zf;
    float gx = 1.f - fx, gy = 1.f - fy, gz = 1.f - fz;
    #pragma unroll
    for (int dz = 0; dz < 2; dz++)
    #pragma unroll
    for (int dy = 0; dy < 2; dy++)
    #pragma unroll
    for (int dx = 0; dx < 2; dx++) {
        int xi = ix + dx, yi = iy + dy, zi = iz + dz;
        if ((unsigned)xi < (unsigned)Wv && (unsigned)yi < (unsigned)Hv &&
            (unsigned)zi < (unsigned)Dv) {
            float wt = (dx ? fx : gx) * (dy ? fy : gy) * (dz ? fz : gz);
            atomicAdd(vol + (zi * Hv + yi) * Wv + xi, wt * val);
        }
    }
}

// ---------------------------------------------------------------------------
// Unchecked fast paths (pixel proven fully interior)
// ---------------------------------------------------------------------------
__device__ __forceinline__ float trigather_fast(const float* __restrict__ vol,
                                                float px, float py, float pz) {
    float xf = floorf(px), yf = floorf(py), zf = floorf(pz);
    int ix = (int)xf, iy = (int)yf, iz = (int)zf;
    float fx = px - xf, fy = py - yf, fz = pz - zf;
    float gx = 1.f - fx, gy = 1.f - fy, gz = 1.f - fz;
    const float* q = vol + ((iz * Hv + iy) << 7) + ix;
    float v000 = __ldg(q),        v001 = __ldg(q + 1);
    float v010 = __ldg(q + Wv),   v011 = __ldg(q + Wv + 1);
    const float* q2 = q + Hv * Wv;
    float v100 = __ldg(q2),       v101 = __ldg(q2 + 1);
    float v110 = __ldg(q2 + Wv),  v111 = __ldg(q2 + Wv + 1);
    float s0 = (v000 * gx + v001 * fx) * gy + (v010 * gx + v011 * fx) * fy;
    float s1 = (v100 * gx + v101 * fx) * gy + (v110 * gx + v111 * fx) * fy;
    return s0 * gz + s1 * fz;
}

__device__ __forceinline__ void triscatter_fast(float* __restrict__ vol,
                                                float px, float py, float pz, float val) {
    float xf = floorf(px), yf = floorf(py), zf = floorf(pz);
    int ix = (int)xf, iy = (int)yf, iz = (int)zf;
    float fx = px - xf, fy = py - yf, fz = pz - zf;
    float gx = 1.f - fx, gy = 1.f - fy, gz = 1.f - fz;
    float* q = vol + ((iz * Hv + iy) << 7) + ix;
    float w0 = val * gz, w1 = val * fz;
    atomicAdd(q,           gx * gy * w0);
    atomicAdd(q + 1,       fx * gy * w0);
    atomicAdd(q + Wv,      gx * fy * w0);
    atomicAdd(q + Wv + 1,  fx * fy * w0);
    float* q2 = q + Hv * Wv;
    atomicAdd(q2,          gx * gy * w1);
    atomicAdd(q2 + 1,      fx * gy * w1);
    atomicAdd(q2 + Wv,     gx * fy * w1);
    atomicAdd(q2 + Wv + 1, fx * fy * w1);
}

// ---------------------------------------------------------------------------
// Fused apply: GATHER -> vout += AtA(vin); else vout += At(src).
// DOT: also accumulate sum(s^2) = p.AtA(p) into *dot_dst (warp reduce, 1 atomic/warp).
// ---------------------------------------------------------------------------
template <bool GATHER, bool DOT>
__global__ void __launch_bounds__(128) apply_kernel(
    const float* __restrict__ theta, const float* __restrict__ psf,
    const float* __restrict__ vin, const float* __restrict__ src,
    float* __restrict__ vout, double* __restrict__ dot_dst)
{
    int tid = blockIdx.x * 128 + threadIdx.x;   // = n*16384 + h*128 + w
    int n = tid >> 14;
    int h = (tid >> 7) & 127;
    int w = tid & 127;
    const float* T = theta + n * 12;
    float R00 = __ldg(T + 0), R01 = __ldg(T + 1),  R02 = __ldg(T + 2),  t0 = __ldg(T + 3);
    float R10 = __ldg(T + 4), R11 = __ldg(T + 5),  R12 = __ldg(T + 6),  t1 = __ldg(T + 7);
    float R20 = __ldg(T + 8), R21 = __ldg(T + 9),  R22 = __ldg(T + 10), t2 = __ldg(T + 11);
    float u = ((float)w - 63.5f) * 1.5f;
    float v = ((float)h - 63.5f) * 1.5f;
    float cx = R00 * u + R01 * v + t0 + 63.5f;
    float cy = R10 * u + R11 * v + t1 + 63.5f;
    float cz = R20 * u + R21 * v + t2 + 63.5f;
    // per-component bound of |R * off| for off in {-1,0,1}^3
    float a0 = fabsf(R00) + fabsf(R01) + fabsf(R02);
    float a1 = fabsf(R10) + fabsf(R11) + fabsf(R12);
    float a2 = fabsf(R20) + fabsf(R21) + fabsf(R22);

    bool fully_out =
        (cx + a0 <= -1.001f) || (cx - a0 >= 128.001f) ||
        (cy + a1 <= -1.001f) || (cy - a1 >= 128.001f) ||
        (cz + a2 <= -1.001f) || (cz - a2 >= 128.001f);
    bool interior =
        (cx - a0 >= 0.001f) && (cx + a0 <= 126.999f) &&
        (cy - a1 >= 0.001f) && (cy + a1 <= 126.999f) &&
        (cz - a2 >= 0.001f) && (cz + a2 <= 126.999f);

    float s = 0.f;
    if (GATHER) {
        if (!fully_out) {
            if (interior) {
                #pragma unroll
                for (int k = 0; k < 27; k++) {
                    const int dx = k % 3 - 1, dy = (k / 3) % 3 - 1, dz = k / 9 - 1;
                    float px = cx + dx * R00 + dy * R01 + dz * R02;
                    float py = cy + dx * R10 + dy * R11 + dz * R12;
                    float pz = cz + dx * R20 + dy * R21 + dz * R22;
                    s += __ldg(psf + k) * trigather_fast(vin, px, py, pz);
                }
            } else {
                #pragma unroll 1
                for (int k = 0; k < 27; k++) {
                    float ox = (float)(k % 3 - 1);
                    float oy = (float)((k / 3) % 3 - 1);
                    float oz = (float)(k / 9 - 1);
                    float px = cx + ox * R00 + oy * R01 + oz * R02;
                    float py = cy + ox * R10 + oy * R11 + oz * R12;
                    float pz = cz + ox * R20 + oy * R21 + oz * R22;
                    s += __ldg(psf + k) * trigather_safe(vin, px, py, pz);
                }
            }
        }
    } else {
        s = __ldg(src + tid);
    }

    if (DOT) {  // all threads participate: no divergence before this point exits
        double d = (double)s * (double)s;
        #pragma unroll
        for (int o = 16; o; o >>= 1) d += __shfl_down_sync(0xffffffffu, d, o);
        if ((threadIdx.x & 31) == 0) atomicAdd(dot_dst, d);
    }

    if (!fully_out && s != 0.f) {
        if (interior) {
            #pragma unroll
            for (int k = 0; k < 27; k++) {
                const int dx = k % 3 - 1, dy = (k / 3) % 3 - 1, dz = k / 9 - 1;
                float px = cx + dx * R00 + dy * R01 + dz * R02;
                float py = cy + dx * R10 + dy * R11 + dz * R12;
                float pz = cz + dx * R20 + dy * R21 + dz * R22;
                triscatter_fast(vout, px, py, pz, __ldg(psf + k) * s);
            }
        } else {
            #pragma unroll 1
            for (int k = 0; k < 27; k++) {
                float ox = (float)(k % 3 - 1);
                float oy = (float)((k / 3) % 3 - 1);
                float oz = (float)(k / 9 - 1);
                float px = cx + ox * R00 + oy * R01 + oz * R02;
                float py = cy + ox * R10 + oy * R11 + oz * R12;
                float pz = cz + ox * R20 + oy * R21 + oz * R22;
                triscatter_safe(vout, px, py, pz, __ldg(psf + k) * s);
            }
        }
    }
}

// ---------------------------------------------------------------------------
// CG plumbing (fused)
// ---------------------------------------------------------------------------
__device__ __forceinline__ void block_reduce_add(double v, double* dst) {
    #pragma unroll
    for (int o = 16; o; o >>= 1) v += __shfl_down_sync(0xffffffffu, v, o);
    __shared__ double sh[8];
    int lane = threadIdx.x & 31, wid = threadIdx.x >> 5;
    if (lane == 0) sh[wid] = v;
    __syncthreads();
    if (wid == 0) {
        v = (lane < 8) ? sh[lane] : 0.0;
        #pragma unroll
        for (int o = 4; o; o >>= 1) v += __shfl_down_sync(0xffffffffu, v, o);
        if (lane == 0) atomicAdd(dst, v);
    }
}

// b=0, Ap=0, x=volume, scalars=0
__global__ void __launch_bounds__(256) setup_kernel(const float* __restrict__ vol) {
    int i = blockIdx.x * 256 + threadIdx.x;
    g_b[i] = 0.f;
    g_Ap[i] = 0.f;
    g_x[i] = vol[i];
    if (i < NIT + 1) g_rr[i] = 0.0;
    if (i >= 64 && i < 64 + NIT) g_pAp[i - 64] = 0.0;
}

// r = p = b - Ap; Ap = 0 (for iter 0); rr0 reduce
__global__ void __launch_bounds__(256) init_r_kernel() {
    int i = blockIdx.x * 256 + threadIdx.x;
    float rv = g_b[i] - g_Ap[i];
    g_r[i] = rv;
    g_p[i] = rv;
    g_Ap[i] = 0.f;
    block_reduce_add((double)rv * (double)rv, &g_rr[0]);
}

// x += alpha p; r -= alpha Ap; rr_{it+1} reduce
__global__ void __launch_bounds__(256) update_xr_kernel(int it) {
    __shared__ float s_alpha;
    if (threadIdx.x == 0) s_alpha = (float)(g_rr[it] / g_pAp[it]);
    __syncthreads();
    float alpha = s_alpha;
    int i = blockIdx.x * 256 + threadIdx.x;
    g_x[i] = g_x[i] + alpha * g_p[i];
    float rv = g_r[i] - alpha * g_Ap[i];
    g_r[i] = rv;
    block_reduce_add((double)rv * (double)rv, &g_rr[it + 1]);
}

// p = r + beta p; Ap = 0 (for next apply)
__global__ void __launch_bounds__(256) update_p_kernel(int it) {
    __shared__ float s_beta;
    if (threadIdx.x == 0) s_beta = (float)(g_rr[it + 1] / g_rr[it]);
    __syncthreads();
    float beta = s_beta;
    int i = blockIdx.x * 256 + threadIdx.x;
    g_p[i] = g_r[i] + beta * g_p[i];
    g_Ap[i] = 0.f;
}

// Last iteration: out = relu(x + alpha p). No r/p update needed.
__global__ void __launch_bounds__(256) final_kernel(float* __restrict__ out) {
    __shared__ float s_alpha;
    if (threadIdx.x == 0) s_alpha = (float)(g_rr[NIT - 1] / g_pAp[NIT - 1]);
    __syncthreads();
    float alpha = s_alpha;
    int i = blockIdx.x * 256 + threadIdx.x;
    out[i] = fmaxf(g_x[i] + alpha * g_p[i], 0.f);
}

// ---------------------------------------------------------------------------
// Launch
// ---------------------------------------------------------------------------
extern "C" void kernel_launch(void* const* d_in, const int* in_sizes, int n_in,
                              void* d_out, int out_size) {
    const float *theta = nullptr, *slices = nullptr, *volume = nullptr, *psf = nullptr;
    for (int i = 0; i < n_in; i++) {
        switch (in_sizes[i]) {
            case 192:     theta  = (const float*)d_in[i]; break;
            case 262144:  slices = (const float*)d_in[i]; break;
            case 2097152: volume = (const float*)d_in[i]; break;
            case 27:      psf    = (const float*)d_in[i]; break;
        }
    }
    float* out = (float*)d_out;

    static float* pb  = nullptr;
    static float* pp  = nullptr;
    static float* px_ = nullptr;
    static float* pAp = nullptr;
    static double* prr = nullptr;
    static double* ppAp = nullptr;
    if (!pb) {
        cudaGetSymbolAddress((void**)&pb,   g_b);
        cudaGetSymbolAddress((void**)&pp,   g_p);
        cudaGetSymbolAddress((void**)&px_,  g_x);
        cudaGetSymbolAddress((void**)&pAp,  g_Ap);
        cudaGetSymbolAddress((void**)&prr,  g_rr);
        cudaGetSymbolAddress((void**)&ppAp, g_pAp);
    }

    const int VB = VOX / 256;    // 8192 blocks
    const int PB = NPIX / 128;   // 2048 blocks

    setup_kernel<<<VB, 256>>>(volume);
    // b = At(slices)
    apply_kernel<false, false><<<PB, 128>>>(theta, psf, nullptr, slices, pb, nullptr);
    // Ap = AtA(x0)
    apply_kernel<true, false><<<PB, 128>>>(theta, psf, px_, nullptr, pAp, nullptr);
    // r = p = b - Ap; Ap = 0; rr0
    init_r_kernel<<<VB, 256>>>();

    for (int it = 0; it < NIT; it++) {
        // Ap = AtA(p); pAp = sum(s^2)
        apply_kernel<true, true><<<PB, 128>>>(theta, psf, pp, nullptr, pAp, ppAp + it);
        if (it == NIT - 1) {
            final_kernel<<<VB, 256>>>(out);
        } else {
            update_xr_kernel<<<VB, 256>>>(it);
            update_p_kernel<<<VB, 256>>>(it);
        }
    }
}

// round 3
// speedup vs baseline: 1.6013x; 1.2105x over previous
#include <cuda_runtime.h>

#define Dv 128
#define Hv 128
#define Wv 128
#define VOX (Dv*Hv*Wv)
#define NV4 (VOX/4)
#define NSL 16
#define NPIX (NSL*128*128)
#define NIT 10

// Scratch (device globals: no runtime allocation allowed)
__device__ float g_b[VOX];
__device__ float g_x[VOX];
__device__ float g_r[VOX];
__device__ float g_p[VOX];
__device__ float g_Ap[VOX];
__device__ double g_rr[NIT + 1];
__device__ double g_pAp[NIT];

// ---------------------------------------------------------------------------
// Guarded trilinear gather (general path, matches reference _corners exactly)
// ---------------------------------------------------------------------------
__device__ __forceinline__ float trigather_safe(const float* __restrict__ vol,
                                                float px, float py, float pz) {
    if (px <= -1.f || py <= -1.f || pz <= -1.f ||
        px >= (float)Wv || py >= (float)Hv || pz >= (float)Dv) return 0.f;
    float xf = floorf(px), yf = floorf(py), zf = floorf(pz);
    int ix = (int)xf, iy = (int)yf, iz = (int)zf;
    float fx = px - xf, fy = py - yf, fz = pz - zf;
    float gx = 1.f - fx, gy = 1.f - fy, gz = 1.f - fz;
    float s = 0.f;
    #pragma unroll
    for (int dz = 0; dz < 2; dz++)
    #pragma unroll
    for (int dy = 0; dy < 2; dy++)
    #pragma unroll
    for (int dx = 0; dx < 2; dx++) {
        int xi = ix + dx, yi = iy + dy, zi = iz + dz;
        if ((unsigned)xi < (unsigned)Wv && (unsigned)yi < (unsigned)Hv &&
            (unsigned)zi < (unsigned)Dv) {
            float wt = (dx ? fx : gx) * (dy ? fy : gy) * (dz ? fz : gz);
            s += wt * __ldg(vol + (zi * Hv + yi) * Wv + xi);
        }
    }
    return s;
}

__device__ __forceinline__ void triscatter_safe(float* __restrict__ vol,
                                                float px, float py, float pz, float val) {
    if (px <= -1.f || py <= -1.f || pz <= -1.f ||
        px >= (float)Wv || py >= (float)Hv || pz >= (float)Dv) return;
    float xf = floorf(px), yf = floorf(py), zf = floorf(pz);
    int ix = (int)xf, iy = (int)yf, iz = (int)zf;
    float fx = px - xf, fy = py - yf, fz = pz - zf;
    float gx = 1.f - fx, gy = 1.f - fy, gz = 1.f - fz;
    #pragma unroll
    for (int dz = 0; dz < 2; dz++)
    #pragma unroll
    for (int dy = 0; dy < 2; dy++)
    #pragma unroll
    for (int dx = 0; dx < 2; dx++) {
        int xi = ix + dx, yi = iy + dy, zi = iz + dz;
        if ((unsigned)xi < (unsigned)Wv && (unsigned)yi < (unsigned)Hv &&
            (unsigned)zi < (unsigned)Dv) {
            float wt = (dx ? fx : gx) * (dy ? fy : gy) * (dz ? fz : gz);
            atomicAdd(vol + (zi * Hv + yi) * Wv + xi, wt * val);
        }
    }
}

// ---------------------------------------------------------------------------
// Unchecked fast paths (pixel proven fully interior)
// ---------------------------------------------------------------------------
__device__ __forceinline__ float trigather_fast(const float* __restrict__ vol,
                                                float px, float py, float pz) {
    float xf = floorf(px), yf = floorf(py), zf = floorf(pz);
    int ix = (int)xf, iy = (int)yf, iz = (int)zf;
    float fx = px - xf, fy = py - yf, fz = pz - zf;
    float gx = 1.f - fx, gy = 1.f - fy, gz = 1.f - fz;
    const float* q = vol + ((iz * Hv + iy) << 7) + ix;
    float v000 = __ldg(q),        v001 = __ldg(q + 1);
    float v010 = __ldg(q + Wv),   v011 = __ldg(q + Wv + 1);
    const float* q2 = q + Hv * Wv;
    float v100 = __ldg(q2),       v101 = __ldg(q2 + 1);
    float v110 = __ldg(q2 + Wv),  v111 = __ldg(q2 + Wv + 1);
    float s0 = (v000 * gx + v001 * fx) * gy + (v010 * gx + v011 * fx) * fy;
    float s1 = (v100 * gx + v101 * fx) * gy + (v110 * gx + v111 * fx) * fy;
    return s0 * gz + s1 * fz;
}

__device__ __forceinline__ void triscatter_fast(float* __restrict__ vol,
                                                float px, float py, float pz, float val) {
    float xf = floorf(px), yf = floorf(py), zf = floorf(pz);
    int ix = (int)xf, iy = (int)yf, iz = (int)zf;
    float fx = px - xf, fy = py - yf, fz = pz - zf;
    float gx = 1.f - fx, gy = 1.f - fy, gz = 1.f - fz;
    float* q = vol + ((iz * Hv + iy) << 7) + ix;
    float w0 = val * gz, w1 = val * fz;
    atomicAdd(q,           gx * gy * w0);
    atomicAdd(q + 1,       fx * gy * w0);
    atomicAdd(q + Wv,      gx * fy * w0);
    atomicAdd(q + Wv + 1,  fx * fy * w0);
    float* q2 = q + Hv * Wv;
    atomicAdd(q2,          gx * gy * w1);
    atomicAdd(q2 + 1,      fx * gy * w1);
    atomicAdd(q2 + Wv,     gx * fy * w1);
    atomicAdd(q2 + Wv + 1, fx * fy * w1);
}

// ---------------------------------------------------------------------------
// Block reduce + single atomic
// ---------------------------------------------------------------------------
template <int NWARP>
__device__ __forceinline__ void block_reduce_add(double v, double* dst) {
    #pragma unroll
    for (int o = 16; o; o >>= 1) v += __shfl_down_sync(0xffffffffu, v, o);
    __shared__ double sh[NWARP];
    int lane = threadIdx.x & 31, wid = threadIdx.x >> 5;
    if (lane == 0) sh[wid] = v;
    __syncthreads();
    if (wid == 0) {
        v = (lane < NWARP) ? sh[lane] : 0.0;
        #pragma unroll
        for (int o = NWARP / 2; o; o >>= 1) v += __shfl_down_sync(0xffffffffu, v, o);
        if (lane == 0) atomicAdd(dst, v);
    }
}

// ---------------------------------------------------------------------------
// Fused apply: GATHER -> vout += AtA(vin); else vout += At(src).
// DOT: also accumulate sum(s^2) = p.AtA(p) into *dot_dst (block reduce).
// ---------------------------------------------------------------------------
template <bool GATHER, bool DOT>
__global__ void __launch_bounds__(128) apply_kernel(
    const float* __restrict__ theta, const float* __restrict__ psf,
    const float* __restrict__ vin, const float* __restrict__ src,
    float* __restrict__ vout, double* __restrict__ dot_dst)
{
    int tid = blockIdx.x * 128 + threadIdx.x;   // = n*16384 + h*128 + w
    int n = tid >> 14;
    int h = (tid >> 7) & 127;
    int w = tid & 127;
    const float* T = theta + n * 12;
    float R00 = __ldg(T + 0), R01 = __ldg(T + 1),  R02 = __ldg(T + 2),  t0 = __ldg(T + 3);
    float R10 = __ldg(T + 4), R11 = __ldg(T + 5),  R12 = __ldg(T + 6),  t1 = __ldg(T + 7);
    float R20 = __ldg(T + 8), R21 = __ldg(T + 9),  R22 = __ldg(T + 10), t2 = __ldg(T + 11);
    float u = ((float)w - 63.5f) * 1.5f;
    float v = ((float)h - 63.5f) * 1.5f;
    float cx = R00 * u + R01 * v + t0 + 63.5f;
    float cy = R10 * u + R11 * v + t1 + 63.5f;
    float cz = R20 * u + R21 * v + t2 + 63.5f;
    // per-component bound of |R * off| for off in {-1,0,1}^3
    float a0 = fabsf(R00) + fabsf(R01) + fabsf(R02);
    float a1 = fabsf(R10) + fabsf(R11) + fabsf(R12);
    float a2 = fabsf(R20) + fabsf(R21) + fabsf(R22);

    bool fully_out =
        (cx + a0 <= -1.001f) || (cx - a0 >= 128.001f) ||
        (cy + a1 <= -1.001f) || (cy - a1 >= 128.001f) ||
        (cz + a2 <= -1.001f) || (cz - a2 >= 128.001f);
    bool interior =
        (cx - a0 >= 0.001f) && (cx + a0 <= 126.999f) &&
        (cy - a1 >= 0.001f) && (cy + a1 <= 126.999f) &&
        (cz - a2 >= 0.001f) && (cz + a2 <= 126.999f);

    float s = 0.f;
    if (GATHER) {
        if (!fully_out) {
            if (interior) {
                #pragma unroll
                for (int k = 0; k < 27; k++) {
                    const int dx = k % 3 - 1, dy = (k / 3) % 3 - 1, dz = k / 9 - 1;
                    float px = cx + dx * R00 + dy * R01 + dz * R02;
                    float py = cy + dx * R10 + dy * R11 + dz * R12;
                    float pz = cz + dx * R20 + dy * R21 + dz * R22;
                    s += __ldg(psf + k) * trigather_fast(vin, px, py, pz);
                }
            } else {
                #pragma unroll 1
                for (int k = 0; k < 27; k++) {
                    float ox = (float)(k % 3 - 1);
                    float oy = (float)((k / 3) % 3 - 1);
                    float oz = (float)(k / 9 - 1);
                    float px = cx + ox * R00 + oy * R01 + oz * R02;
                    float py = cy + ox * R10 + oy * R11 + oz * R12;
                    float pz = cz + ox * R20 + oy * R21 + oz * R22;
                    s += __ldg(psf + k) * trigather_safe(vin, px, py, pz);
                }
            }
        }
    } else {
        s = __ldg(src + tid);
    }

    if (DOT) {  // all threads reach here (no divergent exits above)
        block_reduce_add<4>((double)s * (double)s, dot_dst);
    }

    if (!fully_out && s != 0.f) {
        if (interior) {
            #pragma unroll
            for (int k = 0; k < 27; k++) {
                const int dx = k % 3 - 1, dy = (k / 3) % 3 - 1, dz = k / 9 - 1;
                float px = cx + dx * R00 + dy * R01 + dz * R02;
                float py = cy + dx * R10 + dy * R11 + dz * R12;
                float pz = cz + dx * R20 + dy * R21 + dz * R22;
                triscatter_fast(vout, px, py, pz, __ldg(psf + k) * s);
            }
        } else {
            #pragma unroll 1
            for (int k = 0; k < 27; k++) {
                float ox = (float)(k % 3 - 1);
                float oy = (float)((k / 3) % 3 - 1);
                float oz = (float)(k / 9 - 1);
                float px = cx + ox * R00 + oy * R01 + oz * R02;
                float py = cy + ox * R10 + oy * R11 + oz * R12;
                float pz = cz + ox * R20 + oy * R21 + oz * R22;
                triscatter_safe(vout, px, py, pz, __ldg(psf + k) * s);
            }
        }
    }
}

// ---------------------------------------------------------------------------
// Vectorized CG plumbing: float4 grid-stride, 512 blocks x 256 threads.
// ---------------------------------------------------------------------------
#define VGRID 512
#define VTHREADS 256
#define VSTRIDE (VGRID * VTHREADS)

// b=0, Ap=0, x=volume, scalars=0
__global__ void __launch_bounds__(VTHREADS) setup_kernel(const float4* __restrict__ vol) {
    int i = blockIdx.x * VTHREADS + threadIdx.x;
    float4 z = make_float4(0.f, 0.f, 0.f, 0.f);
    float4* b4  = (float4*)g_b;
    float4* ap4 = (float4*)g_Ap;
    float4* x4  = (float4*)g_x;
    #pragma unroll
    for (int j = i; j < NV4; j += VSTRIDE) {
        b4[j]  = z;
        ap4[j] = z;
        x4[j]  = vol[j];
    }
    if (i < NIT + 1) g_rr[i] = 0.0;
    if (i >= 64 && i < 64 + NIT) g_pAp[i - 64] = 0.0;
}

// r = p = b - Ap; Ap = 0 (for iter 0); rr0 reduce
__global__ void __launch_bounds__(VTHREADS) init_r_kernel() {
    int i = blockIdx.x * VTHREADS + threadIdx.x;
    const float4* b4  = (const float4*)g_b;
    float4* ap4 = (float4*)g_Ap;
    float4* r4  = (float4*)g_r;
    float4* p4  = (float4*)g_p;
    float4 z = make_float4(0.f, 0.f, 0.f, 0.f);
    double acc = 0.0;
    #pragma unroll
    for (int j = i; j < NV4; j += VSTRIDE) {
        float4 b = b4[j], a = ap4[j];
        float4 rv = make_float4(b.x - a.x, b.y - a.y, b.z - a.z, b.w - a.w);
        r4[j] = rv;
        p4[j] = rv;
        ap4[j] = z;
        acc += (double)rv.x * rv.x + (double)rv.y * rv.y +
               (double)rv.z * rv.z + (double)rv.w * rv.w;
    }
    block_reduce_add<8>(acc, &g_rr[0]);
}

// x += alpha p; r -= alpha Ap; rr_{it+1} reduce
__global__ void __launch_bounds__(VTHREADS) update_xr_kernel(int it) {
    __shared__ float s_alpha;
    if (threadIdx.x == 0) s_alpha = (float)(g_rr[it] / g_pAp[it]);
    __syncthreads();
    float alpha = s_alpha;
    int i = blockIdx.x * VTHREADS + threadIdx.x;
    float4* x4  = (float4*)g_x;
    float4* r4  = (float4*)g_r;
    const float4* p4  = (const float4*)g_p;
    const float4* ap4 = (const float4*)g_Ap;
    double acc = 0.0;
    #pragma unroll
    for (int j = i; j < NV4; j += VSTRIDE) {
        float4 x = x4[j], p = p4[j], r = r4[j], a = ap4[j];
        x.x += alpha * p.x; x.y += alpha * p.y; x.z += alpha * p.z; x.w += alpha * p.w;
        r.x -= alpha * a.x; r.y -= alpha * a.y; r.z -= alpha * a.z; r.w -= alpha * a.w;
        x4[j] = x;
        r4[j] = r;
        acc += (double)r.x * r.x + (double)r.y * r.y +
               (double)r.z * r.z + (double)r.w * r.w;
    }
    block_reduce_add<8>(acc, &g_rr[it + 1]);
}

// p = r + beta p; Ap = 0 (for next apply)
__global__ void __launch_bounds__(VTHREADS) update_p_kernel(int it) {
    __shared__ float s_beta;
    if (threadIdx.x == 0) s_beta = (float)(g_rr[it + 1] / g_rr[it]);
    __syncthreads();
    float beta = s_beta;
    int i = blockIdx.x * VTHREADS + threadIdx.x;
    const float4* r4  = (const float4*)g_r;
    float4* p4  = (float4*)g_p;
    float4* ap4 = (float4*)g_Ap;
    float4 z = make_float4(0.f, 0.f, 0.f, 0.f);
    #pragma unroll
    for (int j = i; j < NV4; j += VSTRIDE) {
        float4 r = r4[j], p = p4[j];
        p.x = r.x + beta * p.x; p.y = r.y + beta * p.y;
        p.z = r.z + beta * p.z; p.w = r.w + beta * p.w;
        p4[j] = p;
        ap4[j] = z;
    }
}

// Last iteration: out = relu(x + alpha p). No r/p update needed.
__global__ void __launch_bounds__(VTHREADS) final_kernel(float4* __restrict__ out) {
    __shared__ float s_alpha;
    if (threadIdx.x == 0) s_alpha = (float)(g_rr[NIT - 1] / g_pAp[NIT - 1]);
    __syncthreads();
    float alpha = s_alpha;
    int i = blockIdx.x * VTHREADS + threadIdx.x;
    const float4* x4 = (const float4*)g_x;
    const float4* p4 = (const float4*)g_p;
    #pragma unroll
    for (int j = i; j < NV4; j += VSTRIDE) {
        float4 x = x4[j], p = p4[j];
        out[j] = make_float4(fmaxf(x.x + alpha * p.x, 0.f),
                             fmaxf(x.y + alpha * p.y, 0.f),
                             fmaxf(x.z + alpha * p.z, 0.f),
                             fmaxf(x.w + alpha * p.w, 0.f));
    }
}

// ---------------------------------------------------------------------------
// Launch
// ---------------------------------------------------------------------------
extern "C" void kernel_launch(void* const* d_in, const int* in_sizes, int n_in,
                              void* d_out, int out_size) {
    const float *theta = nullptr, *slices = nullptr, *volume = nullptr, *psf = nullptr;
    for (int i = 0; i < n_in; i++) {
        switch (in_sizes[i]) {
            case 192:     theta  = (const float*)d_in[i]; break;
            case 262144:  slices = (const float*)d_in[i]; break;
            case 2097152: volume = (const float*)d_in[i]; break;
            case 27:      psf    = (const float*)d_in[i]; break;
        }
    }

    static float* pb  = nullptr;
    static float* pp  = nullptr;
    static float* px_ = nullptr;
    static float* pAp = nullptr;
    static double* ppAp = nullptr;
    if (!pb) {
        cudaGetSymbolAddress((void**)&pb,   g_b);
        cudaGetSymbolAddress((void**)&pp,   g_p);
        cudaGetSymbolAddress((void**)&px_,  g_x);
        cudaGetSymbolAddress((void**)&pAp,  g_Ap);
        cudaGetSymbolAddress((void**)&ppAp, g_pAp);
    }

    const int PB = NPIX / 128;   // 2048 blocks

    setup_kernel<<<VGRID, VTHREADS>>>((const float4*)volume);
    // b = At(slices)
    apply_kernel<false, false><<<PB, 128>>>(theta, psf, nullptr, slices, pb, nullptr);
    // Ap = AtA(x0)
    apply_kernel<true, false><<<PB, 128>>>(theta, psf, px_, nullptr, pAp, nullptr);
    // r = p = b - Ap; Ap = 0; rr0
    init_r_kernel<<<VGRID, VTHREADS>>>();

    for (int it = 0; it < NIT; it++) {
        // Ap = AtA(p); pAp = sum(s^2)
        apply_kernel<true, true><<<PB, 128>>>(theta, psf, pp, nullptr, pAp, ppAp + it);
        if (it == NIT - 1) {
            final_kernel<<<VGRID, VTHREADS>>>((float4*)d_out);
        } else {
            update_xr_kernel<<<VGRID, VTHREADS>>>(it);
            update_p_kernel<<<VGRID, VTHREADS>>>(it);
        }
    }
}

// round 4
// speedup vs baseline: 1.6338x; 1.0202x over previous
#include <cuda_runtime.h>

#define Dv 128
#define Hv 128
#define Wv 128
#define VOX (Dv*Hv*Wv)
#define NV4 (VOX/4)
#define NSL 16
#define NPIX (NSL*128*128)
#define NIT 10

// Scratch (device globals: no runtime allocation allowed)
__device__ float g_x[VOX];
__device__ float g_r[VOX];
__device__ float g_p[VOX];
__device__ float g_Ap[VOX];
__device__ double g_rr[NIT + 1];
__device__ double g_pAp[NIT];

// ---------------------------------------------------------------------------
// Guarded trilinear gather/scatter (boundary pixels; matches reference exactly)
// ---------------------------------------------------------------------------
__device__ __forceinline__ float trigather_safe(const float* __restrict__ vol,
                                                float px, float py, float pz) {
    if (px <= -1.f || py <= -1.f || pz <= -1.f ||
        px >= (float)Wv || py >= (float)Hv || pz >= (float)Dv) return 0.f;
    float xf = floorf(px), yf = floorf(py), zf = floorf(pz);
    int ix = (int)xf, iy = (int)yf, iz = (int)zf;
    float fx = px - xf, fy = py - yf, fz = pz - zf;
    float gx = 1.f - fx, gy = 1.f - fy, gz = 1.f - fz;
    float s = 0.f;
    #pragma unroll
    for (int dz = 0; dz < 2; dz++)
    #pragma unroll
    for (int dy = 0; dy < 2; dy++)
    #pragma unroll
    for (int dx = 0; dx < 2; dx++) {
        int xi = ix + dx, yi = iy + dy, zi = iz + dz;
        if ((unsigned)xi < (unsigned)Wv && (unsigned)yi < (unsigned)Hv &&
            (unsigned)zi < (unsigned)Dv) {
            float wt = (dx ? fx : gx) * (dy ? fy : gy) * (dz ? fz : gz);
            s += wt * __ldg(vol + (zi * Hv + yi) * Wv + xi);
        }
    }
    return s;
}

__device__ __forceinline__ void triscatter_safe(float* __restrict__ vol,
                                                float px, float py, float pz, float val) {
    if (px <= -1.f || py <= -1.f || pz <= -1.f ||
        px >= (float)Wv || py >= (float)Hv || pz >= (float)Dv) return;
    float xf = floorf(px), yf = floorf(py), zf = floorf(pz);
    int ix = (int)xf, iy = (int)yf, iz = (int)zf;
    float fx = px - xf, fy = py - yf, fz = pz - zf;
    float gx = 1.f - fx, gy = 1.f - fy, gz = 1.f - fz;
    #pragma unroll
    for (int dz = 0; dz < 2; dz++)
    #pragma unroll
    for (int dy = 0; dy < 2; dy++)
    #pragma unroll
    for (int dx = 0; dx < 2; dx++) {
        int xi = ix + dx, yi = iy + dy, zi = iz + dz;
        if ((unsigned)xi < (unsigned)Wv && (unsigned)yi < (unsigned)Hv &&
            (unsigned)zi < (unsigned)Dv) {
            float wt = (dx ? fx : gx) * (dy ? fy : gy) * (dz ? fz : gz);
            atomicAdd(vol + (zi * Hv + yi) * Wv + xi, wt * val);
        }
    }
}

// ---------------------------------------------------------------------------
// Unchecked fast paths (pixel proven fully interior)
// ---------------------------------------------------------------------------
__device__ __forceinline__ float trigather_fast(const float* __restrict__ vol,
                                                float px, float py, float pz) {
    float xf = floorf(px), yf = floorf(py), zf = floorf(pz);
    int ix = (int)xf, iy = (int)yf, iz = (int)zf;
    float fx = px - xf, fy = py - yf, fz = pz - zf;
    float gx = 1.f - fx, gy = 1.f - fy, gz = 1.f - fz;
    const float* q = vol + ((iz * Hv + iy) << 7) + ix;
    float v000 = __ldg(q),        v001 = __ldg(q + 1);
    float v010 = __ldg(q + Wv),   v011 = __ldg(q + Wv + 1);
    const float* q2 = q + Hv * Wv;
    float v100 = __ldg(q2),       v101 = __ldg(q2 + 1);
    float v110 = __ldg(q2 + Wv),  v111 = __ldg(q2 + Wv + 1);
    float s0 = (v000 * gx + v001 * fx) * gy + (v010 * gx + v011 * fx) * fy;
    float s1 = (v100 * gx + v101 * fx) * gy + (v110 * gx + v111 * fx) * fy;
    return s0 * gz + s1 * fz;
}

__device__ __forceinline__ void triscatter_fast(float* __restrict__ vol,
                                                float px, float py, float pz, float val) {
    float xf = floorf(px), yf = floorf(py), zf = floorf(pz);
    int ix = (int)xf, iy = (int)yf, iz = (int)zf;
    float fx = px - xf, fy = py - yf, fz = pz - zf;
    float gx = 1.f - fx, gy = 1.f - fy, gz = 1.f - fz;
    float* q = vol + ((iz * Hv + iy) << 7) + ix;
    float w0 = val * gz, w1 = val * fz;
    float gxgy = gx * gy, fxgy = fx * gy, gxfy = gx * fy, fxfy = fx * fy;
    atomicAdd(q,           gxgy * w0);
    atomicAdd(q + 1,       fxgy * w0);
    atomicAdd(q + Wv,      gxfy * w0);
    atomicAdd(q + Wv + 1,  fxfy * w0);
    float* q2 = q + Hv * Wv;
    atomicAdd(q2,          gxgy * w1);
    atomicAdd(q2 + 1,      fxgy * w1);
    atomicAdd(q2 + Wv,     gxfy * w1);
    atomicAdd(q2 + Wv + 1, fxfy * w1);
}

// ---------------------------------------------------------------------------
// Block reduce + single atomic
// ---------------------------------------------------------------------------
template <int NWARP>
__device__ __forceinline__ void block_reduce_add(double v, double* dst) {
    #pragma unroll
    for (int o = 16; o; o >>= 1) v += __shfl_down_sync(0xffffffffu, v, o);
    __shared__ double sh[NWARP];
    int lane = threadIdx.x & 31, wid = threadIdx.x >> 5;
    if (lane == 0) sh[wid] = v;
    __syncthreads();
    if (wid == 0) {
        v = (lane < NWARP) ? sh[lane] : 0.0;
        #pragma unroll
        for (int o = NWARP / 2; o; o >>= 1) v += __shfl_down_sync(0xffffffffu, v, o);
        if (lane == 0) atomicAdd(dst, v);
    }
}

// ---------------------------------------------------------------------------
// Fused apply.
// INIT mode:  s = slices[pix] - A(x)[pix];  scatter psf*s into g_r  (r0 = At(slices - A x0))
// ITER mode:  s = A(p)[pix];               scatter psf*s into g_Ap; reduce sum(s^2) = p.AtAp
// Interior fast path uses hierarchically shared sample-point partials.
// ---------------------------------------------------------------------------
template <bool INIT>
__global__ void __launch_bounds__(128) apply_kernel(
    const float* __restrict__ theta, const float* __restrict__ psf,
    const float* __restrict__ vin, const float* __restrict__ src,
    float* __restrict__ vout, double* __restrict__ dot_dst)
{
    int tid = blockIdx.x * 128 + threadIdx.x;   // = n*16384 + h*128 + w
    int n = tid >> 14;
    int h = (tid >> 7) & 127;
    int w = tid & 127;
    const float* T = theta + n * 12;
    float R00 = __ldg(T + 0), R01 = __ldg(T + 1),  R02 = __ldg(T + 2),  t0 = __ldg(T + 3);
    float R10 = __ldg(T + 4), R11 = __ldg(T + 5),  R12 = __ldg(T + 6),  t1 = __ldg(T + 7);
    float R20 = __ldg(T + 8), R21 = __ldg(T + 9),  R22 = __ldg(T + 10), t2 = __ldg(T + 11);
    float u = ((float)w - 63.5f) * 1.5f;
    float v = ((float)h - 63.5f) * 1.5f;
    float cx = R00 * u + R01 * v + t0 + 63.5f;
    float cy = R10 * u + R11 * v + t1 + 63.5f;
    float cz = R20 * u + R21 * v + t2 + 63.5f;
    // per-component bound of |R * off| for off in {-1,0,1}^3
    float a0 = fabsf(R00) + fabsf(R01) + fabsf(R02);
    float a1 = fabsf(R10) + fabsf(R11) + fabsf(R12);
    float a2 = fabsf(R20) + fabsf(R21) + fabsf(R22);

    bool fully_out =
        (cx + a0 <= -1.001f) || (cx - a0 >= 128.001f) ||
        (cy + a1 <= -1.001f) || (cy - a1 >= 128.001f) ||
        (cz + a2 <= -1.001f) || (cz - a2 >= 128.001f);
    bool interior =
        (cx - a0 >= 0.001f) && (cx + a0 <= 126.999f) &&
        (cy - a1 >= 0.001f) && (cy + a1 <= 126.999f) &&
        (cz - a2 >= 0.001f) && (cz + a2 <= 126.999f);

    // ---- gather: s = A(vin) at this pixel ----
    float s = 0.f;
    if (!fully_out) {
        if (interior) {
            #pragma unroll
            for (int dz = 0; dz < 3; dz++) {
                float zx = cx + (float)(dz - 1) * R02;
                float zy = cy + (float)(dz - 1) * R12;
                float zz = cz + (float)(dz - 1) * R22;
                #pragma unroll
                for (int dy = 0; dy < 3; dy++) {
                    float yx = zx + (float)(dy - 1) * R01;
                    float yy = zy + (float)(dy - 1) * R11;
                    float yz = zz + (float)(dy - 1) * R21;
                    #pragma unroll
                    for (int dx = 0; dx < 3; dx++) {
                        float px = yx + (float)(dx - 1) * R00;
                        float py = yy + (float)(dx - 1) * R10;
                        float pz = yz + (float)(dx - 1) * R20;
                        s += __ldg(psf + (dz * 3 + dy) * 3 + dx) *
                             trigather_fast(vin, px, py, pz);
                    }
                }
            }
        } else {
            #pragma unroll 1
            for (int k = 0; k < 27; k++) {
                float ox = (float)(k % 3 - 1);
                float oy = (float)((k / 3) % 3 - 1);
                float oz = (float)(k / 9 - 1);
                float px = cx + ox * R00 + oy * R01 + oz * R02;
                float py = cy + ox * R10 + oy * R11 + oz * R12;
                float pz = cz + ox * R20 + oy * R21 + oz * R22;
                s += __ldg(psf + k) * trigather_safe(vin, px, py, pz);
            }
        }
    }

    if (INIT) {
        s = __ldg(src + tid) - s;     // (slices - A x0) at this pixel
    } else {
        // all threads reach here: block-wide reduce of s^2 = p.AtA(p) contribution
        block_reduce_add<4>((double)s * (double)s, dot_dst);
    }

    // ---- scatter: vout += At(s at this pixel) ----
    if (!fully_out && s != 0.f) {
        if (interior) {
            #pragma unroll
            for (int dz = 0; dz < 3; dz++) {
                float zx = cx + (float)(dz - 1) * R02;
                float zy = cy + (float)(dz - 1) * R12;
                float zz = cz + (float)(dz - 1) * R22;
                #pragma unroll
                for (int dy = 0; dy < 3; dy++) {
                    float yx = zx + (float)(dy - 1) * R01;
                    float yy = zy + (float)(dy - 1) * R11;
                    float yz = zz + (float)(dy - 1) * R21;
                    #pragma unroll
                    for (int dx = 0; dx < 3; dx++) {
                        float px = yx + (float)(dx - 1) * R00;
                        float py = yy + (float)(dx - 1) * R10;
                        float pz = yz + (float)(dx - 1) * R20;
                        triscatter_fast(vout, px, py, pz,
                                        __ldg(psf + (dz * 3 + dy) * 3 + dx) * s);
                    }
                }
            }
        } else {
            #pragma unroll 1
            for (int k = 0; k < 27; k++) {
                float ox = (float)(k % 3 - 1);
                float oy = (float)((k / 3) % 3 - 1);
                float oz = (float)(k / 9 - 1);
                float px = cx + ox * R00 + oy * R01 + oz * R02;
                float py = cy + ox * R10 + oy * R11 + oz * R12;
                float pz = cz + ox * R20 + oy * R21 + oz * R22;
                triscatter_safe(vout, px, py, pz, __ldg(psf + k) * s);
            }
        }
    }
}

// ---------------------------------------------------------------------------
// Vectorized CG plumbing: float4, 512 blocks x 256 threads, FIXED 4-iter unroll.
// ---------------------------------------------------------------------------
#define VGRID 512
#define VTHREADS 256
#define VSTRIDE (VGRID * VTHREADS)
// NV4 == VSTRIDE * 4 exactly

// r=0 (scatter target for apply_init), x=volume, scalars=0
__global__ void __launch_bounds__(VTHREADS) setup_kernel(const float4* __restrict__ vol) {
    int i = blockIdx.x * VTHREADS + threadIdx.x;
    float4 z = make_float4(0.f, 0.f, 0.f, 0.f);
    float4* r4 = (float4*)g_r;
    float4* x4 = (float4*)g_x;
    #pragma unroll
    for (int k = 0; k < 4; k++) {
        int j = i + k * VSTRIDE;
        r4[j] = z;
        x4[j] = vol[j];
    }
    if (i < NIT + 1) g_rr[i] = 0.0;
    if (i >= 64 && i < 64 + NIT) g_pAp[i - 64] = 0.0;
}

// p = r; Ap = 0; rr0 reduce      (r already = b - AtA x0 from apply_init)
__global__ void __launch_bounds__(VTHREADS) init_r_kernel() {
    int i = blockIdx.x * VTHREADS + threadIdx.x;
    const float4* r4 = (const float4*)g_r;
    float4* p4  = (float4*)g_p;
    float4* ap4 = (float4*)g_Ap;
    float4 z = make_float4(0.f, 0.f, 0.f, 0.f);
    double acc = 0.0;
    #pragma unroll
    for (int k = 0; k < 4; k++) {
        int j = i + k * VSTRIDE;
        float4 rv = r4[j];
        p4[j] = rv;
        ap4[j] = z;
        acc += (double)rv.x * rv.x + (double)rv.y * rv.y +
               (double)rv.z * rv.z + (double)rv.w * rv.w;
    }
    block_reduce_add<8>(acc, &g_rr[0]);
}

// x += alpha p; r -= alpha Ap; rr_{it+1} reduce
__global__ void __launch_bounds__(VTHREADS) update_xr_kernel(int it) {
    __shared__ float s_alpha;
    if (threadIdx.x == 0) s_alpha = (float)(g_rr[it] / g_pAp[it]);
    __syncthreads();
    float alpha = s_alpha;
    int i = blockIdx.x * VTHREADS + threadIdx.x;
    float4* x4  = (float4*)g_x;
    float4* r4  = (float4*)g_r;
    const float4* p4  = (const float4*)g_p;
    const float4* ap4 = (const float4*)g_Ap;
    double acc = 0.0;
    #pragma unroll
    for (int k = 0; k < 4; k++) {
        int j = i + k * VSTRIDE;
        float4 x = x4[j], p = p4[j], r = r4[j], a = ap4[j];
        x.x += alpha * p.x; x.y += alpha * p.y; x.z += alpha * p.z; x.w += alpha * p.w;
        r.x -= alpha * a.x; r.y -= alpha * a.y; r.z -= alpha * a.z; r.w -= alpha * a.w;
        x4[j] = x;
        r4[j] = r;
        acc += (double)r.x * r.x + (double)r.y * r.y +
               (double)r.z * r.z + (double)r.w * r.w;
    }
    block_reduce_add<8>(acc, &g_rr[it + 1]);
}

// p = r + beta p; Ap = 0 (for next apply)
__global__ void __launch_bounds__(VTHREADS) update_p_kernel(int it) {
    __shared__ float s_beta;
    if (threadIdx.x == 0) s_beta = (float)(g_rr[it + 1] / g_rr[it]);
    __syncthreads();
    float beta = s_beta;
    int i = blockIdx.x * VTHREADS + threadIdx.x;
    const float4* r4  = (const float4*)g_r;
    float4* p4  = (float4*)g_p;
    float4* ap4 = (float4*)g_Ap;
    float4 z = make_float4(0.f, 0.f, 0.f, 0.f);
    #pragma unroll
    for (int k = 0; k < 4; k++) {
        int j = i + k * VSTRIDE;
        float4 r = r4[j], p = p4[j];
        p.x = r.x + beta * p.x; p.y = r.y + beta * p.y;
        p.z = r.z + beta * p.z; p.w = r.w + beta * p.w;
        p4[j] = p;
        ap4[j] = z;
    }
}

// Last iteration: out = relu(x + alpha p).
__global__ void __launch_bounds__(VTHREADS) final_kernel(float4* __restrict__ out) {
    __shared__ float s_alpha;
    if (threadIdx.x == 0) s_alpha = (float)(g_rr[NIT - 1] / g_pAp[NIT - 1]);
    __syncthreads();
    float alpha = s_alpha;
    int i = blockIdx.x * VTHREADS + threadIdx.x;
    const float4* x4 = (const float4*)g_x;
    const float4* p4 = (const float4*)g_p;
    #pragma unroll
    for (int k = 0; k < 4; k++) {
        int j = i + k * VSTRIDE;
        float4 x = x4[j], p = p4[j];
        out[j] = make_float4(fmaxf(x.x + alpha * p.x, 0.f),
                             fmaxf(x.y + alpha * p.y, 0.f),
                             fmaxf(x.z + alpha * p.z, 0.f),
                             fmaxf(x.w + alpha * p.w, 0.f));
    }
}

// ---------------------------------------------------------------------------
// Launch
// ---------------------------------------------------------------------------
extern "C" void kernel_launch(void* const* d_in, const int* in_sizes, int n_in,
                              void* d_out, int out_size) {
    const float *theta = nullptr, *slices = nullptr, *volume = nullptr, *psf = nullptr;
    for (int i = 0; i < n_in; i++) {
        switch (in_sizes[i]) {
            case 192:     theta  = (const float*)d_in[i]; break;
            case 262144:  slices = (const float*)d_in[i]; break;
            case 2097152: volume = (const float*)d_in[i]; break;
            case 27:      psf    = (const float*)d_in[i]; break;
        }
    }

    static float* pr  = nullptr;
    static float* pp  = nullptr;
    static float* px_ = nullptr;
    static float* pAp = nullptr;
    static double* ppAp = nullptr;
    if (!pr) {
        cudaGetSymbolAddress((void**)&pr,   g_r);
        cudaGetSymbolAddress((void**)&pp,   g_p);
        cudaGetSymbolAddress((void**)&px_,  g_x);
        cudaGetSymbolAddress((void**)&pAp,  g_Ap);
        cudaGetSymbolAddress((void**)&ppAp, g_pAp);
    }

    const int PB = NPIX / 128;   // 2048 blocks

    setup_kernel<<<VGRID, VTHREADS>>>((const float4*)volume);
    // r0 = At(slices - A x0), scattered directly into g_r
    apply_kernel<true><<<PB, 128>>>(theta, psf, px_, slices, pr, nullptr);
    // p = r; Ap = 0; rr0
    init_r_kernel<<<VGRID, VTHREADS>>>();

    for (int it = 0; it < NIT; it++) {
        // Ap = AtA(p); pAp = sum(s^2)
        apply_kernel<false><<<PB, 128>>>(theta, psf, pp, nullptr, pAp, ppAp + it);
        if (it == NIT - 1) {
            final_kernel<<<VGRID, VTHREADS>>>((float4*)d_out);
        } else {
            update_xr_kernel<<<VGRID, VTHREADS>>>(it);
            update_p_kernel<<<VGRID, VTHREADS>>>(it);
        }
    }
}

// round 5
// speedup vs baseline: 1.9391x; 1.1869x over previous
#include <cuda_runtime.h>

#define Dv 128
#define Hv 128
#define Wv 128
#define VOX (Dv*Hv*Wv)
#define NV4 (VOX/4)
#define NSL 16
#define NPIX (NSL*128*128)
#define NIT 10

// Scatter staging box (per 16x8 pixel tile)
#define BX 32
#define BY 20
#define BZ 12
#define BVOL (BX*BY*BZ)

// Scratch (device globals: no runtime allocation allowed)
__device__ float g_x[VOX];
__device__ float g_r[VOX];
__device__ float g_p[VOX];
__device__ float g_Ap[VOX];
__device__ double g_rr[NIT + 1];
__device__ double g_pAp[NIT];

// ---------------------------------------------------------------------------
// Guarded trilinear gather / scatter (fallback paths; match reference exactly)
// ---------------------------------------------------------------------------
__device__ __forceinline__ float trigather_safe(const float* __restrict__ vol,
                                                float px, float py, float pz) {
    if (px <= -1.f || py <= -1.f || pz <= -1.f ||
        px >= (float)Wv || py >= (float)Hv || pz >= (float)Dv) return 0.f;
    float xf = floorf(px), yf = floorf(py), zf = floorf(pz);
    int ix = (int)xf, iy = (int)yf, iz = (int)zf;
    float fx = px - xf, fy = py - yf, fz = pz - zf;
    float gx = 1.f - fx, gy = 1.f - fy, gz = 1.f - fz;
    float s = 0.f;
    #pragma unroll
    for (int dz = 0; dz < 2; dz++)
    #pragma unroll
    for (int dy = 0; dy < 2; dy++)
    #pragma unroll
    for (int dx = 0; dx < 2; dx++) {
        int xi = ix + dx, yi = iy + dy, zi = iz + dz;
        if ((unsigned)xi < (unsigned)Wv && (unsigned)yi < (unsigned)Hv &&
            (unsigned)zi < (unsigned)Dv) {
            float wt = (dx ? fx : gx) * (dy ? fy : gy) * (dz ? fz : gz);
            s += wt * __ldg(vol + (zi * Hv + yi) * Wv + xi);
        }
    }
    return s;
}

__device__ __forceinline__ void triscatter_safe(float* __restrict__ vol,
                                                float px, float py, float pz, float val) {
    if (px <= -1.f || py <= -1.f || pz <= -1.f ||
        px >= (float)Wv || py >= (float)Hv || pz >= (float)Dv) return;
    float xf = floorf(px), yf = floorf(py), zf = floorf(pz);
    int ix = (int)xf, iy = (int)yf, iz = (int)zf;
    float fx = px - xf, fy = py - yf, fz = pz - zf;
    float gx = 1.f - fx, gy = 1.f - fy, gz = 1.f - fz;
    #pragma unroll
    for (int dz = 0; dz < 2; dz++)
    #pragma unroll
    for (int dy = 0; dy < 2; dy++)
    #pragma unroll
    for (int dx = 0; dx < 2; dx++) {
        int xi = ix + dx, yi = iy + dy, zi = iz + dz;
        if ((unsigned)xi < (unsigned)Wv && (unsigned)yi < (unsigned)Hv &&
            (unsigned)zi < (unsigned)Dv) {
            float wt = (dx ? fx : gx) * (dy ? fy : gy) * (dz ? fz : gz);
            atomicAdd(vol + (zi * Hv + yi) * Wv + xi, wt * val);
        }
    }
}

// ---------------------------------------------------------------------------
// Unchecked gather fast path (pixel proven fully interior)
// ---------------------------------------------------------------------------
__device__ __forceinline__ float trigather_fast(const float* __restrict__ vol,
                                                float px, float py, float pz) {
    float xf = floorf(px), yf = floorf(py), zf = floorf(pz);
    int ix = (int)xf, iy = (int)yf, iz = (int)zf;
    float fx = px - xf, fy = py - yf, fz = pz - zf;
    float gx = 1.f - fx, gy = 1.f - fy, gz = 1.f - fz;
    const float* q = vol + ((iz * Hv + iy) << 7) + ix;
    float v000 = __ldg(q),        v001 = __ldg(q + 1);
    float v010 = __ldg(q + Wv),   v011 = __ldg(q + Wv + 1);
    const float* q2 = q + Hv * Wv;
    float v100 = __ldg(q2),       v101 = __ldg(q2 + 1);
    float v110 = __ldg(q2 + Wv),  v111 = __ldg(q2 + Wv + 1);
    float s0 = (v000 * gx + v001 * fx) * gy + (v010 * gx + v011 * fx) * fy;
    float s1 = (v100 * gx + v101 * fx) * gy + (v110 * gx + v111 * fx) * fy;
    return s0 * gz + s1 * fz;
}

// ---------------------------------------------------------------------------
// Block reduce + single atomic
// ---------------------------------------------------------------------------
template <int NWARP>
__device__ __forceinline__ void block_reduce_add(double v, double* dst) {
    #pragma unroll
    for (int o = 16; o; o >>= 1) v += __shfl_down_sync(0xffffffffu, v, o);
    __shared__ double sh[NWARP];
    int lane = threadIdx.x & 31, wid = threadIdx.x >> 5;
    if (lane == 0) sh[wid] = v;
    __syncthreads();
    if (wid == 0) {
        v = (lane < NWARP) ? sh[lane] : 0.0;
        #pragma unroll
        for (int o = NWARP / 2; o; o >>= 1) v += __shfl_down_sync(0xffffffffu, v, o);
        if (lane == 0) atomicAdd(dst, v);
    }
}

// ---------------------------------------------------------------------------
// Fused apply with shared-memory scatter staging.
// Block = 16x8 pixel tile of one slice (128 threads).
// INIT:  s = slices[pix] - A(x)[pix]; scatter psf*s into g_r.
// ITER:  s = A(p)[pix]; scatter psf*s into g_Ap; reduce sum(s^2) = p.AtAp.
// Scatter goes to a smem box covering the tile's full PSF footprint, then one
// clipped flush (volume bounds applied at flush => exact OOB-zero semantics).
// ---------------------------------------------------------------------------
template <bool INIT>
__global__ void __launch_bounds__(128) apply_kernel(
    const float* __restrict__ theta, const float* __restrict__ psf,
    const float* __restrict__ vin, const float* __restrict__ src,
    float* __restrict__ vout, double* __restrict__ dot_dst)
{
    __shared__ __align__(16) float sbox[BVOL];

    int b = blockIdx.x;
    int n   = b >> 7;                 // 128 tiles per slice
    int tyx = b & 127;
    int ty0 = (tyx >> 3) << 3;        // tile row * 8
    int tx0 = (tyx & 7) << 4;         // tile col * 16
    int lx = threadIdx.x & 15, ly = threadIdx.x >> 4;
    int w = tx0 + lx, h = ty0 + ly;
    int pix = (n << 14) + (h << 7) + w;

    const float* T = theta + n * 12;
    float R00 = __ldg(T + 0), R01 = __ldg(T + 1),  R02 = __ldg(T + 2),  t0 = __ldg(T + 3);
    float R10 = __ldg(T + 4), R11 = __ldg(T + 5),  R12 = __ldg(T + 6),  t1 = __ldg(T + 7);
    float R20 = __ldg(T + 8), R21 = __ldg(T + 9),  R22 = __ldg(T + 10), t2 = __ldg(T + 11);

    float u = ((float)w - 63.5f) * 1.5f;
    float v = ((float)h - 63.5f) * 1.5f;
    float cx = R00 * u + R01 * v + t0 + 63.5f;
    float cy = R10 * u + R11 * v + t1 + 63.5f;
    float cz = R20 * u + R21 * v + t2 + 63.5f;

    float a0 = fabsf(R00) + fabsf(R01) + fabsf(R02);
    float a1 = fabsf(R10) + fabsf(R11) + fabsf(R12);
    float a2 = fabsf(R20) + fabsf(R21) + fabsf(R22);

    // ---- uniform tile bounding box of all sample points (+trilinear corner) ----
    float u0 = ((float)tx0 - 63.5f) * 1.5f;
    float v0 = ((float)ty0 - 63.5f) * 1.5f;
    float X00 = R00 * u0 + R01 * v0 + t0 + 63.5f;
    float Y00 = R10 * u0 + R11 * v0 + t1 + 63.5f;
    float Z00 = R20 * u0 + R21 * v0 + t2 + 63.5f;
    const float SI = 22.5f, SJ = 10.5f;   // 15*1.5, 7*1.5
    float eps = 0.01f;
    float mnx = X00 + fminf(0.f, SI * R00) + fminf(0.f, SJ * R01) - a0 - eps;
    float mxx = X00 + fmaxf(0.f, SI * R00) + fmaxf(0.f, SJ * R01) + a0 + eps;
    float mny = Y00 + fminf(0.f, SI * R10) + fminf(0.f, SJ * R11) - a1 - eps;
    float mxy = Y00 + fmaxf(0.f, SI * R10) + fmaxf(0.f, SJ * R11) + a1 + eps;
    float mnz = Z00 + fminf(0.f, SI * R20) + fminf(0.f, SJ * R21) - a2 - eps;
    float mxz = Z00 + fmaxf(0.f, SI * R20) + fmaxf(0.f, SJ * R21) + a2 + eps;
    int bx0 = (int)floorf(mnx), bx1 = (int)floorf(mxx) + 1;
    int by0 = (int)floorf(mny), by1 = (int)floorf(mxy) + 1;
    int bz0 = (int)floorf(mnz), bz1 = (int)floorf(mxz) + 1;

    // whole-tile outside volume -> zero contribution everywhere
    if (bx1 < 0 || bx0 > Wv - 1 || by1 < 0 || by0 > Hv - 1 || bz1 < 0 || bz0 > Dv - 1)
        return;

    bool fit = (bx1 - bx0 < BX) && (by1 - by0 < BY) && (bz1 - bz0 < BZ);

    if (fit) {
        float4* s4 = (float4*)sbox;
        #pragma unroll
        for (int i = threadIdx.x; i < BVOL / 4; i += 128)
            s4[i] = make_float4(0.f, 0.f, 0.f, 0.f);
    }

    // ---- per-pixel gather classification ----
    bool fully_out =
        (cx + a0 <= -1.001f) || (cx - a0 >= 128.001f) ||
        (cy + a1 <= -1.001f) || (cy - a1 >= 128.001f) ||
        (cz + a2 <= -1.001f) || (cz - a2 >= 128.001f);
    bool interior =
        (cx - a0 >= 0.001f) && (cx + a0 <= 126.999f) &&
        (cy - a1 >= 0.001f) && (cy + a1 <= 126.999f) &&
        (cz - a2 >= 0.001f) && (cz + a2 <= 126.999f);

    // ---- gather: s = A(vin) at this pixel ----
    float s = 0.f;
    if (!fully_out) {
        if (interior) {
            #pragma unroll
            for (int dz = 0; dz < 3; dz++) {
                float zx = cx + (float)(dz - 1) * R02;
                float zy = cy + (float)(dz - 1) * R12;
                float zz = cz + (float)(dz - 1) * R22;
                #pragma unroll
                for (int dy = 0; dy < 3; dy++) {
                    float yx = zx + (float)(dy - 1) * R01;
                    float yy = zy + (float)(dy - 1) * R11;
                    float yz = zz + (float)(dy - 1) * R21;
                    #pragma unroll
                    for (int dx = 0; dx < 3; dx++) {
                        float px = yx + (float)(dx - 1) * R00;
                        float py = yy + (float)(dx - 1) * R10;
                        float pz = yz + (float)(dx - 1) * R20;
                        s += __ldg(psf + (dz * 3 + dy) * 3 + dx) *
                             trigather_fast(vin, px, py, pz);
                    }
                }
            }
        } else {
            #pragma unroll 1
            for (int k = 0; k < 27; k++) {
                float ox = (float)(k % 3 - 1);
                float oy = (float)((k / 3) % 3 - 1);
                float oz = (float)(k / 9 - 1);
                float px = cx + ox * R00 + oy * R01 + oz * R02;
                float py = cy + ox * R10 + oy * R11 + oz * R12;
                float pz = cz + ox * R20 + oy * R21 + oz * R22;
                s += __ldg(psf + k) * trigather_safe(vin, px, py, pz);
            }
        }
    }

    if (INIT) {
        s = __ldg(src + pix) - s;     // (slices - A x0) at this pixel
    } else {
        block_reduce_add<4>((double)s * (double)s, dot_dst);  // p.AtA(p)
    }

    // ---- scatter ----
    if (fit) {
        __syncthreads();   // zeroing complete (and reduce's sync already passed)
        if (s != 0.f) {
            #pragma unroll
            for (int dz = 0; dz < 3; dz++) {
                float zx = cx + (float)(dz - 1) * R02;
                float zy = cy + (float)(dz - 1) * R12;
                float zz = cz + (float)(dz - 1) * R22;
                #pragma unroll
                for (int dy = 0; dy < 3; dy++) {
                    float yx = zx + (float)(dy - 1) * R01;
                    float yy = zy + (float)(dy - 1) * R11;
                    float yz = zz + (float)(dy - 1) * R21;
                    #pragma unroll
                    for (int dx = 0; dx < 3; dx++) {
                        float px = yx + (float)(dx - 1) * R00;
                        float py = yy + (float)(dx - 1) * R10;
                        float pz = yz + (float)(dx - 1) * R20;
                        float val = __ldg(psf + (dz * 3 + dy) * 3 + dx) * s;
                        float xf = floorf(px), yf = floorf(py), zf = floorf(pz);
                        int ix = (int)xf - bx0, iy = (int)yf - by0, iz = (int)zf - bz0;
                        float fx = px - xf, fy = py - yf, fz = pz - zf;
                        float gx = 1.f - fx, gy = 1.f - fy, gz = 1.f - fz;
                        if ((unsigned)ix < BX - 1 && (unsigned)iy < BY - 1 &&
                            (unsigned)iz < BZ - 1) {
                            float* q = sbox + (iz * BY + iy) * BX + ix;
                            float w0 = val * gz, w1 = val * fz;
                            float gxgy = gx * gy, fxgy = fx * gy;
                            float gxfy = gx * fy, fxfy = fx * fy;
                            atomicAdd(q,              gxgy * w0);
                            atomicAdd(q + 1,          fxgy * w0);
                            atomicAdd(q + BX,         gxfy * w0);
                            atomicAdd(q + BX + 1,     fxfy * w0);
                            float* q2 = q + BY * BX;
                            atomicAdd(q2,             gxgy * w1);
                            atomicAdd(q2 + 1,         fxgy * w1);
                            atomicAdd(q2 + BX,        gxfy * w1);
                            atomicAdd(q2 + BX + 1,    fxfy * w1);
                        } else {
                            // paranoia path (should not happen given box margins)
                            triscatter_safe(vout, px, py, pz, val);
                        }
                    }
                }
            }
        }
        __syncthreads();   // scatter complete
        // ---- clipped flush: one global atomic per nonzero cell in-volume ----
        #pragma unroll 4
        for (int i = threadIdx.x; i < BVOL; i += 128) {
            float val = sbox[i];
            if (val != 0.f) {
                int gx = bx0 + (i & (BX - 1));
                int gy = by0 + ((i / BX) % BY);
                int gz = bz0 + i / (BX * BY);
                if ((unsigned)gx < (unsigned)Wv && (unsigned)gy < (unsigned)Hv &&
                    (unsigned)gz < (unsigned)Dv)
                    atomicAdd(vout + ((gz * Hv + gy) << 7) + gx, val);
            }
        }
    } else if (!fully_out && s != 0.f) {
        // fallback: direct global scatter (box didn't fit smem)
        #pragma unroll 1
        for (int k = 0; k < 27; k++) {
            float ox = (float)(k % 3 - 1);
            float oy = (float)((k / 3) % 3 - 1);
            float oz = (float)(k / 9 - 1);
            float px = cx + ox * R00 + oy * R01 + oz * R02;
            float py = cy + ox * R10 + oy * R11 + oz * R12;
            float pz = cz + ox * R20 + oy * R21 + oz * R22;
            triscatter_safe(vout, px, py, pz, __ldg(psf + k) * s);
        }
    }
}

// ---------------------------------------------------------------------------
// Vectorized CG plumbing: float4, 512 blocks x 256 threads, fixed 4-iter unroll.
// ---------------------------------------------------------------------------
#define VGRID 512
#define VTHREADS 256
#define VSTRIDE (VGRID * VTHREADS)

__global__ void __launch_bounds__(VTHREADS) setup_kernel(const float4* __restrict__ vol) {
    int i = blockIdx.x * VTHREADS + threadIdx.x;
    float4 z = make_float4(0.f, 0.f, 0.f, 0.f);
    float4* r4 = (float4*)g_r;
    float4* x4 = (float4*)g_x;
    #pragma unroll
    for (int k = 0; k < 4; k++) {
        int j = i + k * VSTRIDE;
        r4[j] = z;
        x4[j] = vol[j];
    }
    if (i < NIT + 1) g_rr[i] = 0.0;
    if (i >= 64 && i < 64 + NIT) g_pAp[i - 64] = 0.0;
}

__global__ void __launch_bounds__(VTHREADS) init_r_kernel() {
    int i = blockIdx.x * VTHREADS + threadIdx.x;
    const float4* r4 = (const float4*)g_r;
    float4* p4  = (float4*)g_p;
    float4* ap4 = (float4*)g_Ap;
    float4 z = make_float4(0.f, 0.f, 0.f, 0.f);
    double acc = 0.0;
    #pragma unroll
    for (int k = 0; k < 4; k++) {
        int j = i + k * VSTRIDE;
        float4 rv = r4[j];
        p4[j] = rv;
        ap4[j] = z;
        acc += (double)rv.x * rv.x + (double)rv.y * rv.y +
               (double)rv.z * rv.z + (double)rv.w * rv.w;
    }
    block_reduce_add<8>(acc, &g_rr[0]);
}

__global__ void __launch_bounds__(VTHREADS) update_xr_kernel(int it) {
    __shared__ float s_alpha;
    if (threadIdx.x == 0) s_alpha = (float)(g_rr[it] / g_pAp[it]);
    __syncthreads();
    float alpha = s_alpha;
    int i = blockIdx.x * VTHREADS + threadIdx.x;
    float4* x4  = (float4*)g_x;
    float4* r4  = (float4*)g_r;
    const float4* p4  = (const float4*)g_p;
    const float4* ap4 = (const float4*)g_Ap;
    double acc = 0.0;
    #pragma unroll
    for (int k = 0; k < 4; k++) {
        int j = i + k * VSTRIDE;
        float4 x = x4[j], p = p4[j], r = r4[j], a = ap4[j];
        x.x += alpha * p.x; x.y += alpha * p.y; x.z += alpha * p.z; x.w += alpha * p.w;
        r.x -= alpha * a.x; r.y -= alpha * a.y; r.z -= alpha * a.z; r.w -= alpha * a.w;
        x4[j] = x;
        r4[j] = r;
        acc += (double)r.x * r.x + (double)r.y * r.y +
               (double)r.z * r.z + (double)r.w * r.w;
    }
    block_reduce_add<8>(acc, &g_rr[it + 1]);
}

__global__ void __launch_bounds__(VTHREADS) update_p_kernel(int it) {
    __shared__ float s_beta;
    if (threadIdx.x == 0) s_beta = (float)(g_rr[it + 1] / g_rr[it]);
    __syncthreads();
    float beta = s_beta;
    int i = blockIdx.x * VTHREADS + threadIdx.x;
    const float4* r4  = (const float4*)g_r;
    float4* p4  = (float4*)g_p;
    float4* ap4 = (float4*)g_Ap;
    float4 z = make_float4(0.f, 0.f, 0.f, 0.f);
    #pragma unroll
    for (int k = 0; k < 4; k++) {
        int j = i + k * VSTRIDE;
        float4 r = r4[j], p = p4[j];
        p.x = r.x + beta * p.x; p.y = r.y + beta * p.y;
        p.z = r.z + beta * p.z; p.w = r.w + beta * p.w;
        p4[j] = p;
        ap4[j] = z;
    }
}

__global__ void __launch_bounds__(VTHREADS) final_kernel(float4* __restrict__ out) {
    __shared__ float s_alpha;
    if (threadIdx.x == 0) s_alpha = (float)(g_rr[NIT - 1] / g_pAp[NIT - 1]);
    __syncthreads();
    float alpha = s_alpha;
    int i = blockIdx.x * VTHREADS + threadIdx.x;
    const float4* x4 = (const float4*)g_x;
    const float4* p4 = (const float4*)g_p;
    #pragma unroll
    for (int k = 0; k < 4; k++) {
        int j = i + k * VSTRIDE;
        float4 x = x4[j], p = p4[j];
        out[j] = make_float4(fmaxf(x.x + alpha * p.x, 0.f),
                             fmaxf(x.y + alpha * p.y, 0.f),
                             fmaxf(x.z + alpha * p.z, 0.f),
                             fmaxf(x.w + alpha * p.w, 0.f));
    }
}

// ---------------------------------------------------------------------------
// Launch
// ---------------------------------------------------------------------------
extern "C" void kernel_launch(void* const* d_in, const int* in_sizes, int n_in,
                              void* d_out, int out_size) {
    const float *theta = nullptr, *slices = nullptr, *volume = nullptr, *psf = nullptr;
    for (int i = 0; i < n_in; i++) {
        switch (in_sizes[i]) {
            case 192:     theta  = (const float*)d_in[i]; break;
            case 262144:  slices = (const float*)d_in[i]; break;
            case 2097152: volume = (const float*)d_in[i]; break;
            case 27:      psf    = (const float*)d_in[i]; break;
        }
    }

    static float* pr  = nullptr;
    static float* pp  = nullptr;
    static float* px_ = nullptr;
    static float* pAp = nullptr;
    static double* ppAp = nullptr;
    if (!pr) {
        cudaGetSymbolAddress((void**)&pr,   g_r);
        cudaGetSymbolAddress((void**)&pp,   g_p);
        cudaGetSymbolAddress((void**)&px_,  g_x);
        cudaGetSymbolAddress((void**)&pAp,  g_Ap);
        cudaGetSymbolAddress((void**)&ppAp, g_pAp);
    }

    const int PB = NPIX / 128;   // 2048 tile blocks

    setup_kernel<<<VGRID, VTHREADS>>>((const float4*)volume);
    // r0 = At(slices - A x0), scattered directly into g_r
    apply_kernel<true><<<PB, 128>>>(theta, psf, px_, slices, pr, nullptr);
    // p = r; Ap = 0; rr0
    init_r_kernel<<<VGRID, VTHREADS>>>();

    for (int it = 0; it < NIT; it++) {
        // Ap = AtA(p); pAp = sum(s^2)
        apply_kernel<false><<<PB, 128>>>(theta, psf, pp, nullptr, pAp, ppAp + it);
        if (it == NIT - 1) {
            final_kernel<<<VGRID, VTHREADS>>>((float4*)d_out);
        } else {
            update_xr_kernel<<<VGRID, VTHREADS>>>(it);
            update_p_kernel<<<VGRID, VTHREADS>>>(it);
        }
    }
}

// round 6
// speedup vs baseline: 1.9661x; 1.0139x over previous
#include <cuda_runtime.h>

#define Dv 128
#define Hv 128
#define Wv 128
#define VOX (Dv*Hv*Wv)
#define NV4 (VOX/4)
#define NSL 16
#define NPIX (NSL*128*128)
#define NIT 10

// Scatter staging box (per 16x8 pixel tile)
#define BX 32
#define BY 20
#define BZ 12
#define BVOL (BX*BY*BZ)

// Scratch (device globals: no runtime allocation allowed)
__device__ float g_x[VOX];
__device__ float g_r[VOX];
__device__ float g_p[VOX];
__device__ float g_Ap[VOX];
__device__ double g_rr[NIT + 1];
__device__ double g_pAp[NIT];
__device__ int g_bar_count = 0;
__device__ int g_bar_gen = 0;

__constant__ float c_psf[27];

// ---------------------------------------------------------------------------
// Guarded trilinear gather / scatter (fallback paths; match reference exactly)
// ---------------------------------------------------------------------------
__device__ __forceinline__ float trigather_safe(const float* __restrict__ vol,
                                                float px, float py, float pz) {
    if (px <= -1.f || py <= -1.f || pz <= -1.f ||
        px >= (float)Wv || py >= (float)Hv || pz >= (float)Dv) return 0.f;
    float xf = floorf(px), yf = floorf(py), zf = floorf(pz);
    int ix = (int)xf, iy = (int)yf, iz = (int)zf;
    float fx = px - xf, fy = py - yf, fz = pz - zf;
    float gx = 1.f - fx, gy = 1.f - fy, gz = 1.f - fz;
    float s = 0.f;
    #pragma unroll
    for (int dz = 0; dz < 2; dz++)
    #pragma unroll
    for (int dy = 0; dy < 2; dy++)
    #pragma unroll
    for (int dx = 0; dx < 2; dx++) {
        int xi = ix + dx, yi = iy + dy, zi = iz + dz;
        if ((unsigned)xi < (unsigned)Wv && (unsigned)yi < (unsigned)Hv &&
            (unsigned)zi < (unsigned)Dv) {
            float wt = (dx ? fx : gx) * (dy ? fy : gy) * (dz ? fz : gz);
            s += wt * __ldg(vol + (zi * Hv + yi) * Wv + xi);
        }
    }
    return s;
}

__device__ __forceinline__ void triscatter_safe(float* __restrict__ vol,
                                                float px, float py, float pz, float val) {
    if (px <= -1.f || py <= -1.f || pz <= -1.f ||
        px >= (float)Wv || py >= (float)Hv || pz >= (float)Dv) return;
    float xf = floorf(px), yf = floorf(py), zf = floorf(pz);
    int ix = (int)xf, iy = (int)yf, iz = (int)zf;
    float fx = px - xf, fy = py - yf, fz = pz - zf;
    float gx = 1.f - fx, gy = 1.f - fy, gz = 1.f - fz;
    #pragma unroll
    for (int dz = 0; dz < 2; dz++)
    #pragma unroll
    for (int dy = 0; dy < 2; dy++)
    #pragma unroll
    for (int dx = 0; dx < 2; dx++) {
        int xi = ix + dx, yi = iy + dy, zi = iz + dz;
        if ((unsigned)xi < (unsigned)Wv && (unsigned)yi < (unsigned)Hv &&
            (unsigned)zi < (unsigned)Dv) {
            float wt = (dx ? fx : gx) * (dy ? fy : gy) * (dz ? fz : gz);
            atomicAdd(vol + (zi * Hv + yi) * Wv + xi, wt * val);
        }
    }
}

__device__ __forceinline__ float trigather_fast(const float* __restrict__ vol,
                                                float px, float py, float pz) {
    float xf = floorf(px), yf = floorf(py), zf = floorf(pz);
    int ix = (int)xf, iy = (int)yf, iz = (int)zf;
    float fx = px - xf, fy = py - yf, fz = pz - zf;
    float gx = 1.f - fx, gy = 1.f - fy, gz = 1.f - fz;
    const float* q = vol + ((iz * Hv + iy) << 7) + ix;
    float v000 = __ldg(q),        v001 = __ldg(q + 1);
    float v010 = __ldg(q + Wv),   v011 = __ldg(q + Wv + 1);
    const float* q2 = q + Hv * Wv;
    float v100 = __ldg(q2),       v101 = __ldg(q2 + 1);
    float v110 = __ldg(q2 + Wv),  v111 = __ldg(q2 + Wv + 1);
    float s0 = (v000 * gx + v001 * fx) * gy + (v010 * gx + v011 * fx) * fy;
    float s1 = (v100 * gx + v101 * fx) * gy + (v110 * gx + v111 * fx) * fy;
    return s0 * gz + s1 * fz;
}

// ---------------------------------------------------------------------------
// Block reduce + single atomic
// ---------------------------------------------------------------------------
template <int NWARP>
__device__ __forceinline__ void block_reduce_add(double v, double* dst) {
    #pragma unroll
    for (int o = 16; o; o >>= 1) v += __shfl_down_sync(0xffffffffu, v, o);
    __shared__ double sh[NWARP];
    int lane = threadIdx.x & 31, wid = threadIdx.x >> 5;
    if (lane == 0) sh[wid] = v;
    __syncthreads();
    if (wid == 0) {
        v = (lane < NWARP) ? sh[lane] : 0.0;
        #pragma unroll
        for (int o = NWARP / 2; o; o >>= 1) v += __shfl_down_sync(0xffffffffu, v, o);
        if (lane == 0) atomicAdd(dst, v);
    }
}

// ---------------------------------------------------------------------------
// Software grid barrier (all blocks guaranteed resident for the update kernel)
// ---------------------------------------------------------------------------
__device__ __forceinline__ void grid_barrier(int nblocks) {
    __syncthreads();
    if (threadIdx.x == 0) {
        __threadfence();
        int my_gen = *(volatile int*)&g_bar_gen;
        int ticket = atomicAdd(&g_bar_count, 1);
        if (ticket == nblocks - 1) {
            g_bar_count = 0;
            __threadfence();
            atomicAdd(&g_bar_gen, 1);
        } else {
            while (*(volatile int*)&g_bar_gen == my_gen) { }
        }
        __threadfence();
    }
    __syncthreads();
}

// ---------------------------------------------------------------------------
// Fused apply with shared-memory scatter staging. Block = 16x8 pixel tile.
// INIT:  s = slices[pix] - A(x)[pix]; scatter psf*s into g_r.
// ITER:  s = A(p)[pix]; scatter psf*s into g_Ap; reduce sum(s^2) = p.AtAp.
// ---------------------------------------------------------------------------
template <bool INIT>
__global__ void __launch_bounds__(128) apply_kernel(
    const float* __restrict__ theta,
    const float* __restrict__ vin, const float* __restrict__ src,
    float* __restrict__ vout, double* __restrict__ dot_dst)
{
    __shared__ __align__(16) float sbox[BVOL];

    int b = blockIdx.x;
    int n   = b >> 7;
    int tyx = b & 127;
    int ty0 = (tyx >> 3) << 3;
    int tx0 = (tyx & 7) << 4;
    int lx = threadIdx.x & 15, ly = threadIdx.x >> 4;
    int w = tx0 + lx, h = ty0 + ly;
    int pix = (n << 14) + (h << 7) + w;

    const float* T = theta + n * 12;
    float R00 = __ldg(T + 0), R01 = __ldg(T + 1),  R02 = __ldg(T + 2),  t0 = __ldg(T + 3);
    float R10 = __ldg(T + 4), R11 = __ldg(T + 5),  R12 = __ldg(T + 6),  t1 = __ldg(T + 7);
    float R20 = __ldg(T + 8), R21 = __ldg(T + 9),  R22 = __ldg(T + 10), t2 = __ldg(T + 11);

    float u = ((float)w - 63.5f) * 1.5f;
    float v = ((float)h - 63.5f) * 1.5f;
    float cx = R00 * u + R01 * v + t0 + 63.5f;
    float cy = R10 * u + R11 * v + t1 + 63.5f;
    float cz = R20 * u + R21 * v + t2 + 63.5f;

    float a0 = fabsf(R00) + fabsf(R01) + fabsf(R02);
    float a1 = fabsf(R10) + fabsf(R11) + fabsf(R12);
    float a2 = fabsf(R20) + fabsf(R21) + fabsf(R22);

    // uniform tile bounding box of all sample points (+trilinear corner)
    float u0 = ((float)tx0 - 63.5f) * 1.5f;
    float v0 = ((float)ty0 - 63.5f) * 1.5f;
    float X00 = R00 * u0 + R01 * v0 + t0 + 63.5f;
    float Y00 = R10 * u0 + R11 * v0 + t1 + 63.5f;
    float Z00 = R20 * u0 + R21 * v0 + t2 + 63.5f;
    const float SI = 22.5f, SJ = 10.5f;
    float eps = 0.01f;
    float mnx = X00 + fminf(0.f, SI * R00) + fminf(0.f, SJ * R01) - a0 - eps;
    float mxx = X00 + fmaxf(0.f, SI * R00) + fmaxf(0.f, SJ * R01) + a0 + eps;
    float mny = Y00 + fminf(0.f, SI * R10) + fminf(0.f, SJ * R11) - a1 - eps;
    float mxy = Y00 + fmaxf(0.f, SI * R10) + fmaxf(0.f, SJ * R11) + a1 + eps;
    float mnz = Z00 + fminf(0.f, SI * R20) + fminf(0.f, SJ * R21) - a2 - eps;
    float mxz = Z00 + fmaxf(0.f, SI * R20) + fmaxf(0.f, SJ * R21) + a2 + eps;
    int bx0 = (int)floorf(mnx), bx1 = (int)floorf(mxx) + 1;
    int by0 = (int)floorf(mny), by1 = (int)floorf(mxy) + 1;
    int bz0 = (int)floorf(mnz), bz1 = (int)floorf(mxz) + 1;

    if (bx1 < 0 || bx0 > Wv - 1 || by1 < 0 || by0 > Hv - 1 || bz1 < 0 || bz0 > Dv - 1)
        return;

    bool fit = (bx1 - bx0 < BX) && (by1 - by0 < BY) && (bz1 - bz0 < BZ);
    int nzp = min(bz1 - bz0 + 2, BZ);           // active z-planes in sbox
    int ncell = nzp * (BY * BX);                // cells actually touched

    if (fit) {
        float4* s4 = (float4*)sbox;
        int n4 = ncell >> 2;
        for (int i = threadIdx.x; i < n4; i += 128)
            s4[i] = make_float4(0.f, 0.f, 0.f, 0.f);
    }

    bool fully_out =
        (cx + a0 <= -1.001f) || (cx - a0 >= 128.001f) ||
        (cy + a1 <= -1.001f) || (cy - a1 >= 128.001f) ||
        (cz + a2 <= -1.001f) || (cz - a2 >= 128.001f);
    bool interior =
        (cx - a0 >= 0.001f) && (cx + a0 <= 126.999f) &&
        (cy - a1 >= 0.001f) && (cy + a1 <= 126.999f) &&
        (cz - a2 >= 0.001f) && (cz + a2 <= 126.999f);

    // ---- gather: s = A(vin) at this pixel ----
    float s = 0.f;
    if (!fully_out) {
        if (interior) {
            #pragma unroll
            for (int dz = 0; dz < 3; dz++) {
                float zx = cx + (float)(dz - 1) * R02;
                float zy = cy + (float)(dz - 1) * R12;
                float zz = cz + (float)(dz - 1) * R22;
                #pragma unroll
                for (int dy = 0; dy < 3; dy++) {
                    float yx = zx + (float)(dy - 1) * R01;
                    float yy = zy + (float)(dy - 1) * R11;
                    float yz = zz + (float)(dy - 1) * R21;
                    #pragma unroll
                    for (int dx = 0; dx < 3; dx++) {
                        float px = yx + (float)(dx - 1) * R00;
                        float py = yy + (float)(dx - 1) * R10;
                        float pz = yz + (float)(dx - 1) * R20;
                        s += c_psf[(dz * 3 + dy) * 3 + dx] *
                             trigather_fast(vin, px, py, pz);
                    }
                }
            }
        } else {
            #pragma unroll 1
            for (int k = 0; k < 27; k++) {
                float ox = (float)(k % 3 - 1);
                float oy = (float)((k / 3) % 3 - 1);
                float oz = (float)(k / 9 - 1);
                float px = cx + ox * R00 + oy * R01 + oz * R02;
                float py = cy + ox * R10 + oy * R11 + oz * R12;
                float pz = cz + ox * R20 + oy * R21 + oz * R22;
                s += c_psf[k] * trigather_safe(vin, px, py, pz);
            }
        }
    }

    if (INIT) {
        s = __ldg(src + pix) - s;
    } else {
        block_reduce_add<4>((double)s * (double)s, dot_dst);
    }

    // ---- scatter ----
    if (fit) {
        __syncthreads();
        if (s != 0.f) {
            #pragma unroll
            for (int dz = 0; dz < 3; dz++) {
                float zx = cx + (float)(dz - 1) * R02;
                float zy = cy + (float)(dz - 1) * R12;
                float zz = cz + (float)(dz - 1) * R22;
                #pragma unroll
                for (int dy = 0; dy < 3; dy++) {
                    float yx = zx + (float)(dy - 1) * R01;
                    float yy = zy + (float)(dy - 1) * R11;
                    float yz = zz + (float)(dy - 1) * R21;
                    #pragma unroll
                    for (int dx = 0; dx < 3; dx++) {
                        float px = yx + (float)(dx - 1) * R00;
                        float py = yy + (float)(dx - 1) * R10;
                        float pz = yz + (float)(dx - 1) * R20;
                        float val = c_psf[(dz * 3 + dy) * 3 + dx] * s;
                        float xf = floorf(px), yf = floorf(py), zf = floorf(pz);
                        int ix = (int)xf - bx0, iy = (int)yf - by0, iz = (int)zf - bz0;
                        float fx = px - xf, fy = py - yf, fz = pz - zf;
                        float gx = 1.f - fx, gy = 1.f - fy, gz = 1.f - fz;
                        if ((unsigned)ix < BX - 1 && (unsigned)iy < BY - 1 &&
                            (unsigned)iz < BZ - 1) {
                            float* q = sbox + (iz * BY + iy) * BX + ix;
                            float w0 = val * gz, w1 = val * fz;
                            float gxgy = gx * gy, fxgy = fx * gy;
                            float gxfy = gx * fy, fxfy = fx * fy;
                            atomicAdd(q,              gxgy * w0);
                            atomicAdd(q + 1,          fxgy * w0);
                            atomicAdd(q + BX,         gxfy * w0);
                            atomicAdd(q + BX + 1,     fxfy * w0);
                            float* q2 = q + BY * BX;
                            atomicAdd(q2,             gxgy * w1);
                            atomicAdd(q2 + 1,         fxgy * w1);
                            atomicAdd(q2 + BX,        gxfy * w1);
                            atomicAdd(q2 + BX + 1,    fxfy * w1);
                        } else {
                            triscatter_safe(vout, px, py, pz, val);
                        }
                    }
                }
            }
        }
        __syncthreads();
        // clipped flush over active cells only
        for (int i = threadIdx.x; i < ncell; i += 128) {
            float val = sbox[i];
            if (val != 0.f) {
                int gx = bx0 + (i & (BX - 1));
                int gy = by0 + ((i / BX) % BY);
                int gz = bz0 + i / (BX * BY);
                if ((unsigned)gx < (unsigned)Wv && (unsigned)gy < (unsigned)Hv &&
                    (unsigned)gz < (unsigned)Dv)
                    atomicAdd(vout + ((gz * Hv + gy) << 7) + gx, val);
            }
        }
    } else if (!fully_out && s != 0.f) {
        #pragma unroll 1
        for (int k = 0; k < 27; k++) {
            float ox = (float)(k % 3 - 1);
            float oy = (float)((k / 3) % 3 - 1);
            float oz = (float)(k / 9 - 1);
            float px = cx + ox * R00 + oy * R01 + oz * R02;
            float py = cy + ox * R10 + oy * R11 + oz * R12;
            float pz = cz + ox * R20 + oy * R21 + oz * R22;
            triscatter_safe(vout, px, py, pz, c_psf[k] * s);
        }
    }
}

// ---------------------------------------------------------------------------
// Vectorized CG plumbing: float4, 512 blocks x 256 threads, fixed 4-iter unroll.
// ---------------------------------------------------------------------------
#define VGRID 512
#define VTHREADS 256
#define VSTRIDE (VGRID * VTHREADS)

__global__ void __launch_bounds__(VTHREADS) setup_kernel(const float4* __restrict__ vol) {
    int i = blockIdx.x * VTHREADS + threadIdx.x;
    float4 z = make_float4(0.f, 0.f, 0.f, 0.f);
    float4* r4 = (float4*)g_r;
    float4* x4 = (float4*)g_x;
    #pragma unroll
    for (int k = 0; k < 4; k++) {
        int j = i + k * VSTRIDE;
        r4[j] = z;
        x4[j] = vol[j];
    }
    if (i < NIT + 1) g_rr[i] = 0.0;
    if (i >= 64 && i < 64 + NIT) g_pAp[i - 64] = 0.0;
}

__global__ void __launch_bounds__(VTHREADS) init_r_kernel() {
    int i = blockIdx.x * VTHREADS + threadIdx.x;
    const float4* r4 = (const float4*)g_r;
    float4* p4  = (float4*)g_p;
    float4* ap4 = (float4*)g_Ap;
    float4 z = make_float4(0.f, 0.f, 0.f, 0.f);
    double acc = 0.0;
    #pragma unroll
    for (int k = 0; k < 4; k++) {
        int j = i + k * VSTRIDE;
        float4 rv = r4[j];
        p4[j] = rv;
        ap4[j] = z;
        acc += (double)rv.x * rv.x + (double)rv.y * rv.y +
               (double)rv.z * rv.z + (double)rv.w * rv.w;
    }
    block_reduce_add<8>(acc, &g_rr[0]);
}

// Fused update: phase1 (x,r,rr reduce) -> grid barrier -> phase2 (beta, p, Ap=0)
__global__ void __launch_bounds__(VTHREADS) fused_update_kernel(int it) {
    __shared__ float s_alpha;
    if (threadIdx.x == 0) s_alpha = (float)(g_rr[it] / g_pAp[it]);
    __syncthreads();
    float alpha = s_alpha;
    int i = blockIdx.x * VTHREADS + threadIdx.x;
    float4* x4  = (float4*)g_x;
    float4* r4  = (float4*)g_r;
    float4* p4  = (float4*)g_p;
    float4* ap4 = (float4*)g_Ap;
    double acc = 0.0;
    float4 rloc[4];
    #pragma unroll
    for (int k = 0; k < 4; k++) {
        int j = i + k * VSTRIDE;
        float4 x = x4[j], p = p4[j], r = r4[j], a = ap4[j];
        x.x += alpha * p.x; x.y += alpha * p.y; x.z += alpha * p.z; x.w += alpha * p.w;
        r.x -= alpha * a.x; r.y -= alpha * a.y; r.z -= alpha * a.z; r.w -= alpha * a.w;
        x4[j] = x;
        r4[j] = r;
        rloc[k] = r;
        acc += (double)r.x * r.x + (double)r.y * r.y +
               (double)r.z * r.z + (double)r.w * r.w;
    }
    block_reduce_add<8>(acc, &g_rr[it + 1]);

    grid_barrier(VGRID);

    __shared__ float s_beta;
    if (threadIdx.x == 0) {
        double rrn = *(volatile double*)&g_rr[it + 1];
        s_beta = (float)(rrn / g_rr[it]);
    }
    __syncthreads();
    float beta = s_beta;
    float4 z = make_float4(0.f, 0.f, 0.f, 0.f);
    #pragma unroll
    for (int k = 0; k < 4; k++) {
        int j = i + k * VSTRIDE;
        float4 r = rloc[k], p = p4[j];
        p.x = r.x + beta * p.x; p.y = r.y + beta * p.y;
        p.z = r.z + beta * p.z; p.w = r.w + beta * p.w;
        p4[j] = p;
        ap4[j] = z;
    }
}

__global__ void __launch_bounds__(VTHREADS) final_kernel(float4* __restrict__ out) {
    __shared__ float s_alpha;
    if (threadIdx.x == 0) s_alpha = (float)(g_rr[NIT - 1] / g_pAp[NIT - 1]);
    __syncthreads();
    float alpha = s_alpha;
    int i = blockIdx.x * VTHREADS + threadIdx.x;
    const float4* x4 = (const float4*)g_x;
    const float4* p4 = (const float4*)g_p;
    #pragma unroll
    for (int k = 0; k < 4; k++) {
        int j = i + k * VSTRIDE;
        float4 x = x4[j], p = p4[j];
        out[j] = make_float4(fmaxf(x.x + alpha * p.x, 0.f),
                             fmaxf(x.y + alpha * p.y, 0.f),
                             fmaxf(x.z + alpha * p.z, 0.f),
                             fmaxf(x.w + alpha * p.w, 0.f));
    }
}

// ---------------------------------------------------------------------------
// Launch
// ---------------------------------------------------------------------------
extern "C" void kernel_launch(void* const* d_in, const int* in_sizes, int n_in,
                              void* d_out, int out_size) {
    const float *theta = nullptr, *slices = nullptr, *volume = nullptr, *psf = nullptr;
    for (int i = 0; i < n_in; i++) {
        switch (in_sizes[i]) {
            case 192:     theta  = (const float*)d_in[i]; break;
            case 262144:  slices = (const float*)d_in[i]; break;
            case 2097152: volume = (const float*)d_in[i]; break;
            case 27:      psf    = (const float*)d_in[i]; break;
        }
    }

    static float* pr  = nullptr;
    static float* pp  = nullptr;
    static float* px_ = nullptr;
    static float* pAp = nullptr;
    static double* ppAp = nullptr;
    if (!pr) {
        cudaGetSymbolAddress((void**)&pr,   g_r);
        cudaGetSymbolAddress((void**)&pp,   g_p);
        cudaGetSymbolAddress((void**)&px_,  g_x);
        cudaGetSymbolAddress((void**)&pAp,  g_Ap);
        cudaGetSymbolAddress((void**)&ppAp, g_pAp);
    }

    const int PB = NPIX / 128;   // 2048 tile blocks

    // psf -> constant memory (D2D async copy; graph-capturable)
    cudaMemcpyToSymbolAsync(c_psf, psf, 27 * sizeof(float), 0,
                            cudaMemcpyDeviceToDevice, 0);

    setup_kernel<<<VGRID, VTHREADS>>>((const float4*)volume);
    // r0 = At(slices - A x0), scattered directly into g_r
    apply_kernel<true><<<PB, 128>>>(theta, px_, slices, pr, nullptr);
    // p = r; Ap = 0; rr0
    init_r_kernel<<<VGRID, VTHREADS>>>();

    for (int it = 0; it < NIT; it++) {
        // Ap = AtA(p); pAp = sum(s^2)
        apply_kernel<false><<<PB, 128>>>(theta, pp, nullptr, pAp, ppAp + it);
        if (it == NIT - 1) {
            final_kernel<<<VGRID, VTHREADS>>>((float4*)d_out);
        } else {
            fused_update_kernel<<<VGRID, VTHREADS>>>(it);
        }
    }
}

// round 7
// speedup vs baseline: 2.0518x; 1.0436x over previous
#include <cuda_runtime.h>

#define Dv 128
#define Hv 128
#define Wv 128
#define VOX (Dv*Hv*Wv)
#define NV4 (VOX/4)
#define NSL 16
#define NPIX (NSL*128*128)
#define NIT 10

// Scatter staging box (per 16x16 pixel tile) — dynamic smem (56 KB)
#define BX 32
#define BY 32
#define BZ 14
#define BVOL (BX*BY*BZ)
#define APPLY_THREADS 256

// Scratch (device globals: no runtime allocation allowed)
__device__ float g_x[VOX];
__device__ float g_r[VOX];
__device__ float g_p[VOX];
__device__ float g_Ap[VOX];
__device__ double g_rr[NIT + 1];
__device__ double g_pAp[NIT];
__device__ int g_bar_count = 0;
__device__ int g_bar_gen = 0;

__constant__ float c_psf[27];

// ---------------------------------------------------------------------------
// Guarded trilinear gather / scatter (fallback paths; match reference exactly)
// ---------------------------------------------------------------------------
__device__ __forceinline__ float trigather_safe(const float* __restrict__ vol,
                                                float px, float py, float pz) {
    if (px <= -1.f || py <= -1.f || pz <= -1.f ||
        px >= (float)Wv || py >= (float)Hv || pz >= (float)Dv) return 0.f;
    float xf = floorf(px), yf = floorf(py), zf = floorf(pz);
    int ix = (int)xf, iy = (int)yf, iz = (int)zf;
    float fx = px - xf, fy = py - yf, fz = pz - zf;
    float gx = 1.f - fx, gy = 1.f - fy, gz = 1.f - fz;
    float s = 0.f;
    #pragma unroll
    for (int dz = 0; dz < 2; dz++)
    #pragma unroll
    for (int dy = 0; dy < 2; dy++)
    #pragma unroll
    for (int dx = 0; dx < 2; dx++) {
        int xi = ix + dx, yi = iy + dy, zi = iz + dz;
        if ((unsigned)xi < (unsigned)Wv && (unsigned)yi < (unsigned)Hv &&
            (unsigned)zi < (unsigned)Dv) {
            float wt = (dx ? fx : gx) * (dy ? fy : gy) * (dz ? fz : gz);
            s += wt * __ldg(vol + (zi * Hv + yi) * Wv + xi);
        }
    }
    return s;
}

__device__ __forceinline__ void triscatter_safe(float* __restrict__ vol,
                                                float px, float py, float pz, float val) {
    if (px <= -1.f || py <= -1.f || pz <= -1.f ||
        px >= (float)Wv || py >= (float)Hv || pz >= (float)Dv) return;
    float xf = floorf(px), yf = floorf(py), zf = floorf(pz);
    int ix = (int)xf, iy = (int)yf, iz = (int)zf;
    float fx = px - xf, fy = py - yf, fz = pz - zf;
    float gx = 1.f - fx, gy = 1.f - fy, gz = 1.f - fz;
    #pragma unroll
    for (int dz = 0; dz < 2; dz++)
    #pragma unroll
    for (int dy = 0; dy < 2; dy++)
    #pragma unroll
    for (int dx = 0; dx < 2; dx++) {
        int xi = ix + dx, yi = iy + dy, zi = iz + dz;
        if ((unsigned)xi < (unsigned)Wv && (unsigned)yi < (unsigned)Hv &&
            (unsigned)zi < (unsigned)Dv) {
            float wt = (dx ? fx : gx) * (dy ? fy : gy) * (dz ? fz : gz);
            atomicAdd(vol + (zi * Hv + yi) * Wv + xi, wt * val);
        }
    }
}

__device__ __forceinline__ float trigather_fast(const float* __restrict__ vol,
                                                float px, float py, float pz) {
    float xf = floorf(px), yf = floorf(py), zf = floorf(pz);
    int ix = (int)xf, iy = (int)yf, iz = (int)zf;
    float fx = px - xf, fy = py - yf, fz = pz - zf;
    float gx = 1.f - fx, gy = 1.f - fy, gz = 1.f - fz;
    const float* q = vol + ((iz * Hv + iy) << 7) + ix;
    float v000 = __ldg(q),        v001 = __ldg(q + 1);
    float v010 = __ldg(q + Wv),   v011 = __ldg(q + Wv + 1);
    const float* q2 = q + Hv * Wv;
    float v100 = __ldg(q2),       v101 = __ldg(q2 + 1);
    float v110 = __ldg(q2 + Wv),  v111 = __ldg(q2 + Wv + 1);
    float s0 = (v000 * gx + v001 * fx) * gy + (v010 * gx + v011 * fx) * fy;
    float s1 = (v100 * gx + v101 * fx) * gy + (v110 * gx + v111 * fx) * fy;
    return s0 * gz + s1 * fz;
}

// ---------------------------------------------------------------------------
// Block reduce + single atomic
// ---------------------------------------------------------------------------
template <int NWARP>
__device__ __forceinline__ void block_reduce_add(double v, double* dst) {
    #pragma unroll
    for (int o = 16; o; o >>= 1) v += __shfl_down_sync(0xffffffffu, v, o);
    __shared__ double sh[NWARP];
    int lane = threadIdx.x & 31, wid = threadIdx.x >> 5;
    if (lane == 0) sh[wid] = v;
    __syncthreads();
    if (wid == 0) {
        v = (lane < NWARP) ? sh[lane] : 0.0;
        #pragma unroll
        for (int o = NWARP / 2; o; o >>= 1) v += __shfl_down_sync(0xffffffffu, v, o);
        if (lane == 0) atomicAdd(dst, v);
    }
}

// ---------------------------------------------------------------------------
// Software grid barrier
// ---------------------------------------------------------------------------
__device__ __forceinline__ void grid_barrier(int nblocks) {
    __syncthreads();
    if (threadIdx.x == 0) {
        __threadfence();
        int my_gen = *(volatile int*)&g_bar_gen;
        int ticket = atomicAdd(&g_bar_count, 1);
        if (ticket == nblocks - 1) {
            g_bar_count = 0;
            __threadfence();
            atomicAdd(&g_bar_gen, 1);
        } else {
            while (*(volatile int*)&g_bar_gen == my_gen) { }
        }
        __threadfence();
    }
    __syncthreads();
}

// ---------------------------------------------------------------------------
// Fused apply with shared-memory scatter staging. Block = 16x16 pixel tile,
// 256 threads, dynamic smem box 32x32x14.
// INIT:  s = slices[pix] - A(x)[pix]; scatter psf*s into g_r.
// ITER:  s = A(p)[pix]; scatter psf*s into g_Ap; reduce sum(s^2) = p.AtAp.
// ---------------------------------------------------------------------------
template <bool INIT>
__global__ void __launch_bounds__(APPLY_THREADS) apply_kernel(
    const float* __restrict__ theta,
    const float* __restrict__ vin, const float* __restrict__ src,
    float* __restrict__ vout, double* __restrict__ dot_dst)
{
    extern __shared__ __align__(16) float sbox[];

    int b = blockIdx.x;
    int n   = b >> 6;                  // 64 tiles per slice
    int tyx = b & 63;
    int ty0 = (tyx >> 3) << 4;         // tile row * 16
    int tx0 = (tyx & 7) << 4;          // tile col * 16
    int lx = threadIdx.x & 15, ly = threadIdx.x >> 4;
    int w = tx0 + lx, h = ty0 + ly;
    int pix = (n << 14) + (h << 7) + w;

    const float* T = theta + n * 12;
    float R00 = __ldg(T + 0), R01 = __ldg(T + 1),  R02 = __ldg(T + 2),  t0 = __ldg(T + 3);
    float R10 = __ldg(T + 4), R11 = __ldg(T + 5),  R12 = __ldg(T + 6),  t1 = __ldg(T + 7);
    float R20 = __ldg(T + 8), R21 = __ldg(T + 9),  R22 = __ldg(T + 10), t2 = __ldg(T + 11);

    float u = ((float)w - 63.5f) * 1.5f;
    float v = ((float)h - 63.5f) * 1.5f;
    float cx = R00 * u + R01 * v + t0 + 63.5f;
    float cy = R10 * u + R11 * v + t1 + 63.5f;
    float cz = R20 * u + R21 * v + t2 + 63.5f;

    float a0 = fabsf(R00) + fabsf(R01) + fabsf(R02);
    float a1 = fabsf(R10) + fabsf(R11) + fabsf(R12);
    float a2 = fabsf(R20) + fabsf(R21) + fabsf(R22);

    // uniform tile bounding box of all sample points (+trilinear corner)
    float u0 = ((float)tx0 - 63.5f) * 1.5f;
    float v0 = ((float)ty0 - 63.5f) * 1.5f;
    float X00 = R00 * u0 + R01 * v0 + t0 + 63.5f;
    float Y00 = R10 * u0 + R11 * v0 + t1 + 63.5f;
    float Z00 = R20 * u0 + R21 * v0 + t2 + 63.5f;
    const float SI = 22.5f, SJ = 22.5f;    // 15*1.5 in both tile dims
    float eps = 0.01f;
    float mnx = X00 + fminf(0.f, SI * R00) + fminf(0.f, SJ * R01) - a0 - eps;
    float mxx = X00 + fmaxf(0.f, SI * R00) + fmaxf(0.f, SJ * R01) + a0 + eps;
    float mny = Y00 + fminf(0.f, SI * R10) + fminf(0.f, SJ * R11) - a1 - eps;
    float mxy = Y00 + fmaxf(0.f, SI * R10) + fmaxf(0.f, SJ * R11) + a1 + eps;
    float mnz = Z00 + fminf(0.f, SI * R20) + fminf(0.f, SJ * R21) - a2 - eps;
    float mxz = Z00 + fmaxf(0.f, SI * R20) + fmaxf(0.f, SJ * R21) + a2 + eps;
    int bx0 = (int)floorf(mnx), bx1 = (int)floorf(mxx) + 1;
    int by0 = (int)floorf(mny), by1 = (int)floorf(mxy) + 1;
    int bz0 = (int)floorf(mnz), bz1 = (int)floorf(mxz) + 1;

    if (bx1 < 0 || bx0 > Wv - 1 || by1 < 0 || by0 > Hv - 1 || bz1 < 0 || bz0 > Dv - 1)
        return;

    bool fit = (bx1 - bx0 < BX) && (by1 - by0 < BY) && (bz1 - bz0 < BZ);
    int nzp = min(bz1 - bz0 + 2, BZ);
    int ncell = nzp * (BY * BX);

    if (fit) {
        float4* s4 = (float4*)sbox;
        int n4 = ncell >> 2;
        for (int i = threadIdx.x; i < n4; i += APPLY_THREADS)
            s4[i] = make_float4(0.f, 0.f, 0.f, 0.f);
    }

    bool fully_out =
        (cx + a0 <= -1.001f) || (cx - a0 >= 128.001f) ||
        (cy + a1 <= -1.001f) || (cy - a1 >= 128.001f) ||
        (cz + a2 <= -1.001f) || (cz - a2 >= 128.001f);
    bool interior =
        (cx - a0 >= 0.001f) && (cx + a0 <= 126.999f) &&
        (cy - a1 >= 0.001f) && (cy + a1 <= 126.999f) &&
        (cz - a2 >= 0.001f) && (cz + a2 <= 126.999f);

    // ---- gather: s = A(vin) at this pixel ----
    float s = 0.f;
    if (!fully_out) {
        if (interior) {
            #pragma unroll
            for (int dz = 0; dz < 3; dz++) {
                float zx = cx + (float)(dz - 1) * R02;
                float zy = cy + (float)(dz - 1) * R12;
                float zz = cz + (float)(dz - 1) * R22;
                #pragma unroll
                for (int dy = 0; dy < 3; dy++) {
                    float yx = zx + (float)(dy - 1) * R01;
                    float yy = zy + (float)(dy - 1) * R11;
                    float yz = zz + (float)(dy - 1) * R21;
                    #pragma unroll
                    for (int dx = 0; dx < 3; dx++) {
                        float px = yx + (float)(dx - 1) * R00;
                        float py = yy + (float)(dx - 1) * R10;
                        float pz = yz + (float)(dx - 1) * R20;
                        s += c_psf[(dz * 3 + dy) * 3 + dx] *
                             trigather_fast(vin, px, py, pz);
                    }
                }
            }
        } else {
            #pragma unroll 3
            for (int k = 0; k < 27; k++) {
                float ox = (float)(k % 3 - 1);
                float oy = (float)((k / 3) % 3 - 1);
                float oz = (float)(k / 9 - 1);
                float px = cx + ox * R00 + oy * R01 + oz * R02;
                float py = cy + ox * R10 + oy * R11 + oz * R12;
                float pz = cz + ox * R20 + oy * R21 + oz * R22;
                s += c_psf[k] * trigather_safe(vin, px, py, pz);
            }
        }
    }

    if (INIT) {
        s = __ldg(src + pix) - s;
    } else {
        block_reduce_add<8>((double)s * (double)s, dot_dst);
    }

    // ---- scatter ----
    if (fit) {
        __syncthreads();
        if (s != 0.f) {
            #pragma unroll
            for (int dz = 0; dz < 3; dz++) {
                float zx = cx + (float)(dz - 1) * R02;
                float zy = cy + (float)(dz - 1) * R12;
                float zz = cz + (float)(dz - 1) * R22;
                #pragma unroll
                for (int dy = 0; dy < 3; dy++) {
                    float yx = zx + (float)(dy - 1) * R01;
                    float yy = zy + (float)(dy - 1) * R11;
                    float yz = zz + (float)(dy - 1) * R21;
                    #pragma unroll
                    for (int dx = 0; dx < 3; dx++) {
                        float px = yx + (float)(dx - 1) * R00;
                        float py = yy + (float)(dx - 1) * R10;
                        float pz = yz + (float)(dx - 1) * R20;
                        float val = c_psf[(dz * 3 + dy) * 3 + dx] * s;
                        float xf = floorf(px), yf = floorf(py), zf = floorf(pz);
                        int ix = (int)xf - bx0, iy = (int)yf - by0, iz = (int)zf - bz0;
                        float fx = px - xf, fy = py - yf, fz = pz - zf;
                        float gx = 1.f - fx, gy = 1.f - fy, gz = 1.f - fz;
                        if ((unsigned)ix < BX - 1 && (unsigned)iy < BY - 1 &&
                            (unsigned)iz < BZ - 1) {
                            float* q = sbox + (iz * BY + iy) * BX + ix;
                            float w0 = val * gz, w1 = val * fz;
                            float gxgy = gx * gy, fxgy = fx * gy;
                            float gxfy = gx * fy, fxfy = fx * fy;
                            atomicAdd(q,              gxgy * w0);
                            atomicAdd(q + 1,          fxgy * w0);
                            atomicAdd(q + BX,         gxfy * w0);
                            atomicAdd(q + BX + 1,     fxfy * w0);
                            float* q2 = q + BY * BX;
                            atomicAdd(q2,             gxgy * w1);
                            atomicAdd(q2 + 1,         fxgy * w1);
                            atomicAdd(q2 + BX,        gxfy * w1);
                            atomicAdd(q2 + BX + 1,    fxfy * w1);
                        } else {
                            triscatter_safe(vout, px, py, pz, val);
                        }
                    }
                }
            }
        }
        __syncthreads();
        // clipped flush over active cells only
        for (int i = threadIdx.x; i < ncell; i += APPLY_THREADS) {
            float val = sbox[i];
            if (val != 0.f) {
                int gx = bx0 + (i & (BX - 1));
                int gy = by0 + ((i >> 5) & (BY - 1));
                int gz = bz0 + (i >> 10);
                if ((unsigned)gx < (unsigned)Wv && (unsigned)gy < (unsigned)Hv &&
                    (unsigned)gz < (unsigned)Dv)
                    atomicAdd(vout + ((gz * Hv + gy) << 7) + gx, val);
            }
        }
    } else if (!fully_out && s != 0.f) {
        #pragma unroll 3
        for (int k = 0; k < 27; k++) {
            float ox = (float)(k % 3 - 1);
            float oy = (float)((k / 3) % 3 - 1);
            float oz = (float)(k / 9 - 1);
            float px = cx + ox * R00 + oy * R01 + oz * R02;
            float py = cy + ox * R10 + oy * R11 + oz * R12;
            float pz = cz + ox * R20 + oy * R21 + oz * R22;
            triscatter_safe(vout, px, py, pz, c_psf[k] * s);
        }
    }
}

// ---------------------------------------------------------------------------
// Vectorized CG plumbing: float4, 512 blocks x 256 threads, fixed 4-iter unroll.
// ---------------------------------------------------------------------------
#define VGRID 512
#define VTHREADS 256
#define VSTRIDE (VGRID * VTHREADS)

__global__ void __launch_bounds__(VTHREADS) setup_kernel(const float4* __restrict__ vol) {
    int i = blockIdx.x * VTHREADS + threadIdx.x;
    float4 z = make_float4(0.f, 0.f, 0.f, 0.f);
    float4* r4 = (float4*)g_r;
    float4* x4 = (float4*)g_x;
    #pragma unroll
    for (int k = 0; k < 4; k++) {
        int j = i + k * VSTRIDE;
        r4[j] = z;
        x4[j] = vol[j];
    }
    if (i < NIT + 1) g_rr[i] = 0.0;
    if (i >= 64 && i < 64 + NIT) g_pAp[i - 64] = 0.0;
}

__global__ void __launch_bounds__(VTHREADS) init_r_kernel() {
    int i = blockIdx.x * VTHREADS + threadIdx.x;
    const float4* r4 = (const float4*)g_r;
    float4* p4  = (float4*)g_p;
    float4* ap4 = (float4*)g_Ap;
    float4 z = make_float4(0.f, 0.f, 0.f, 0.f);
    double acc = 0.0;
    #pragma unroll
    for (int k = 0; k < 4; k++) {
        int j = i + k * VSTRIDE;
        float4 rv = r4[j];
        p4[j] = rv;
        ap4[j] = z;
        acc += (double)rv.x * rv.x + (double)rv.y * rv.y +
               (double)rv.z * rv.z + (double)rv.w * rv.w;
    }
    block_reduce_add<8>(acc, &g_rr[0]);
}

// Fused update: phase1 (x,r,rr reduce) -> grid barrier -> phase2 (beta, p, Ap=0)
__global__ void __launch_bounds__(VTHREADS) fused_update_kernel(int it) {
    __shared__ float s_alpha;
    if (threadIdx.x == 0) s_alpha = (float)(g_rr[it] / g_pAp[it]);
    __syncthreads();
    float alpha = s_alpha;
    int i = blockIdx.x * VTHREADS + threadIdx.x;
    float4* x4  = (float4*)g_x;
    float4* r4  = (float4*)g_r;
    float4* p4  = (float4*)g_p;
    float4* ap4 = (float4*)g_Ap;
    double acc = 0.0;
    float4 rloc[4];
    #pragma unroll
    for (int k = 0; k < 4; k++) {
        int j = i + k * VSTRIDE;
        float4 x = x4[j], p = p4[j], r = r4[j], a = ap4[j];
        x.x += alpha * p.x; x.y += alpha * p.y; x.z += alpha * p.z; x.w += alpha * p.w;
        r.x -= alpha * a.x; r.y -= alpha * a.y; r.z -= alpha * a.z; r.w -= alpha * a.w;
        x4[j] = x;
        r4[j] = r;
        rloc[k] = r;
        acc += (double)r.x * r.x + (double)r.y * r.y +
               (double)r.z * r.z + (double)r.w * r.w;
    }
    block_reduce_add<8>(acc, &g_rr[it + 1]);

    grid_barrier(VGRID);

    __shared__ float s_beta;
    if (threadIdx.x == 0) {
        double rrn = *(volatile double*)&g_rr[it + 1];
        s_beta = (float)(rrn / g_rr[it]);
    }
    __syncthreads();
    float beta = s_beta;
    float4 z = make_float4(0.f, 0.f, 0.f, 0.f);
    #pragma unroll
    for (int k = 0; k < 4; k++) {
        int j = i + k * VSTRIDE;
        float4 r = rloc[k], p = p4[j];
        p.x = r.x + beta * p.x; p.y = r.y + beta * p.y;
        p.z = r.z + beta * p.z; p.w = r.w + beta * p.w;
        p4[j] = p;
        ap4[j] = z;
    }
}

__global__ void __launch_bounds__(VTHREADS) final_kernel(float4* __restrict__ out) {
    __shared__ float s_alpha;
    if (threadIdx.x == 0) s_alpha = (float)(g_rr[NIT - 1] / g_pAp[NIT - 1]);
    __syncthreads();
    float alpha = s_alpha;
    int i = blockIdx.x * VTHREADS + threadIdx.x;
    const float4* x4 = (const float4*)g_x;
    const float4* p4 = (const float4*)g_p;
    #pragma unroll
    for (int k = 0; k < 4; k++) {
        int j = i + k * VSTRIDE;
        float4 x = x4[j], p = p4[j];
        out[j] = make_float4(fmaxf(x.x + alpha * p.x, 0.f),
                             fmaxf(x.y + alpha * p.y, 0.f),
                             fmaxf(x.z + alpha * p.z, 0.f),
                             fmaxf(x.w + alpha * p.w, 0.f));
    }
}

// ---------------------------------------------------------------------------
// Launch
// ---------------------------------------------------------------------------
extern "C" void kernel_launch(void* const* d_in, const int* in_sizes, int n_in,
                              void* d_out, int out_size) {
    const float *theta = nullptr, *slices = nullptr, *volume = nullptr, *psf = nullptr;
    for (int i = 0; i < n_in; i++) {
        switch (in_sizes[i]) {
            case 192:     theta  = (const float*)d_in[i]; break;
            case 262144:  slices = (const float*)d_in[i]; break;
            case 2097152: volume = (const float*)d_in[i]; break;
            case 27:      psf    = (const float*)d_in[i]; break;
        }
    }

    const int SBYTES = BVOL * (int)sizeof(float);   // 57344

    static float* pr  = nullptr;
    static float* pp  = nullptr;
    static float* px_ = nullptr;
    static float* pAp = nullptr;
    static double* ppAp = nullptr;
    if (!pr) {
        cudaGetSymbolAddress((void**)&pr,   g_r);
        cudaGetSymbolAddress((void**)&pp,   g_p);
        cudaGetSymbolAddress((void**)&px_,  g_x);
        cudaGetSymbolAddress((void**)&pAp,  g_Ap);
        cudaGetSymbolAddress((void**)&ppAp, g_pAp);
        cudaFuncSetAttribute(apply_kernel<true>,
                             cudaFuncAttributeMaxDynamicSharedMemorySize, SBYTES);
        cudaFuncSetAttribute(apply_kernel<false>,
                             cudaFuncAttributeMaxDynamicSharedMemorySize, SBYTES);
    }

    const int PB = NPIX / 256;   // 1024 tile blocks (16x16 tiles)

    // psf -> constant memory (D2D async copy; graph-capturable)
    cudaMemcpyToSymbolAsync(c_psf, psf, 27 * sizeof(float), 0,
                            cudaMemcpyDeviceToDevice, 0);

    setup_kernel<<<VGRID, VTHREADS>>>((const float4*)volume);
    // r0 = At(slices - A x0), scattered directly into g_r
    apply_kernel<true><<<PB, APPLY_THREADS, SBYTES>>>(theta, px_, slices, pr, nullptr);
    // p = r; Ap = 0; rr0
    init_r_kernel<<<VGRID, VTHREADS>>>();

    for (int it = 0; it < NIT; it++) {
        // Ap = AtA(p); pAp = sum(s^2)
        apply_kernel<false><<<PB, APPLY_THREADS, SBYTES>>>(theta, pp, nullptr, pAp, ppAp + it);
        if (it == NIT - 1) {
            final_kernel<<<VGRID, VTHREADS>>>((float4*)d_out);
        } else {
            fused_update_kernel<<<VGRID, VTHREADS>>>(it);
        }
    }
}

// round 8
// speedup vs baseline: 2.2825x; 1.1125x over previous
#include <cuda_runtime.h>

#define Dv 128
#define Hv 128
#define Wv 128
#define VOX (Dv*Hv*Wv)
#define NV4 (VOX/4)
#define NSL 16
#define NPIX (NSL*128*128)
#define NIT 10

// Scatter staging box (per 16x16 pixel tile) — dynamic smem (48 KB -> 4 blocks/SM)
#define BX 32
#define BY 32
#define BZ 12
#define BVOL (BX*BY*BZ)
#define APPLY_THREADS 256

// Scratch (device globals: no runtime allocation allowed)
__device__ float g_x[VOX];
__device__ float g_r[VOX];
__device__ float g_p[VOX];
__device__ float g_Ap[VOX];
__device__ double g_rr[NIT + 1];
__device__ double g_pAp[NIT];
__device__ int g_bar_count = 0;
__device__ int g_bar_gen = 0;

__constant__ float c_psf[27];

// ---------------------------------------------------------------------------
// Guarded trilinear gather / scatter (fallback paths; match reference exactly)
// ---------------------------------------------------------------------------
__device__ __forceinline__ float trigather_safe(const float* __restrict__ vol,
                                                float px, float py, float pz) {
    if (px <= -1.f || py <= -1.f || pz <= -1.f ||
        px >= (float)Wv || py >= (float)Hv || pz >= (float)Dv) return 0.f;
    float xf = floorf(px), yf = floorf(py), zf = floorf(pz);
    int ix = (int)xf, iy = (int)yf, iz = (int)zf;
    float fx = px - xf, fy = py - yf, fz = pz - zf;
    float gx = 1.f - fx, gy = 1.f - fy, gz = 1.f - fz;
    float s = 0.f;
    #pragma unroll
    for (int dz = 0; dz < 2; dz++)
    #pragma unroll
    for (int dy = 0; dy < 2; dy++)
    #pragma unroll
    for (int dx = 0; dx < 2; dx++) {
        int xi = ix + dx, yi = iy + dy, zi = iz + dz;
        if ((unsigned)xi < (unsigned)Wv && (unsigned)yi < (unsigned)Hv &&
            (unsigned)zi < (unsigned)Dv) {
            float wt = (dx ? fx : gx) * (dy ? fy : gy) * (dz ? fz : gz);
            s += wt * __ldg(vol + (zi * Hv + yi) * Wv + xi);
        }
    }
    return s;
}

__device__ __forceinline__ void triscatter_safe(float* __restrict__ vol,
                                                float px, float py, float pz, float val) {
    if (px <= -1.f || py <= -1.f || pz <= -1.f ||
        px >= (float)Wv || py >= (float)Hv || pz >= (float)Dv) return;
    float xf = floorf(px), yf = floorf(py), zf = floorf(pz);
    int ix = (int)xf, iy = (int)yf, iz = (int)zf;
    float fx = px - xf, fy = py - yf, fz = pz - zf;
    float gx = 1.f - fx, gy = 1.f - fy, gz = 1.f - fz;
    #pragma unroll
    for (int dz = 0; dz < 2; dz++)
    #pragma unroll
    for (int dy = 0; dy < 2; dy++)
    #pragma unroll
    for (int dx = 0; dx < 2; dx++) {
        int xi = ix + dx, yi = iy + dy, zi = iz + dz;
        if ((unsigned)xi < (unsigned)Wv && (unsigned)yi < (unsigned)Hv &&
            (unsigned)zi < (unsigned)Dv) {
            float wt = (dx ? fx : gx) * (dy ? fy : gy) * (dz ? fz : gz);
            atomicAdd(vol + (zi * Hv + yi) * Wv + xi, wt * val);
        }
    }
}

__device__ __forceinline__ float trigather_fast(const float* __restrict__ vol,
                                                float px, float py, float pz) {
    float xf = floorf(px), yf = floorf(py), zf = floorf(pz);
    int ix = (int)xf, iy = (int)yf, iz = (int)zf;
    float fx = px - xf, fy = py - yf, fz = pz - zf;
    float gx = 1.f - fx, gy = 1.f - fy, gz = 1.f - fz;
    const float* q = vol + ((iz * Hv + iy) << 7) + ix;
    float v000 = __ldg(q),        v001 = __ldg(q + 1);
    float v010 = __ldg(q + Wv),   v011 = __ldg(q + Wv + 1);
    const float* q2 = q + Hv * Wv;
    float v100 = __ldg(q2),       v101 = __ldg(q2 + 1);
    float v110 = __ldg(q2 + Wv),  v111 = __ldg(q2 + Wv + 1);
    float s0 = (v000 * gx + v001 * fx) * gy + (v010 * gx + v011 * fx) * fy;
    float s1 = (v100 * gx + v101 * fx) * gy + (v110 * gx + v111 * fx) * fy;
    return s0 * gz + s1 * fz;
}

// ---------------------------------------------------------------------------
// Block reduce + single atomic
// ---------------------------------------------------------------------------
template <int NWARP>
__device__ __forceinline__ void block_reduce_add(double v, double* dst) {
    #pragma unroll
    for (int o = 16; o; o >>= 1) v += __shfl_down_sync(0xffffffffu, v, o);
    __shared__ double sh[NWARP];
    int lane = threadIdx.x & 31, wid = threadIdx.x >> 5;
    if (lane == 0) sh[wid] = v;
    __syncthreads();
    if (wid == 0) {
        v = (lane < NWARP) ? sh[lane] : 0.0;
        #pragma unroll
        for (int o = NWARP / 2; o; o >>= 1) v += __shfl_down_sync(0xffffffffu, v, o);
        if (lane == 0) atomicAdd(dst, v);
    }
}

// ---------------------------------------------------------------------------
// Software grid barrier
// ---------------------------------------------------------------------------
__device__ __forceinline__ void grid_barrier(int nblocks) {
    __syncthreads();
    if (threadIdx.x == 0) {
        __threadfence();
        int my_gen = *(volatile int*)&g_bar_gen;
        int ticket = atomicAdd(&g_bar_count, 1);
        if (ticket == nblocks - 1) {
            g_bar_count = 0;
            __threadfence();
            atomicAdd(&g_bar_gen, 1);
        } else {
            while (*(volatile int*)&g_bar_gen == my_gen) { }
        }
        __threadfence();
    }
    __syncthreads();
}

// ---------------------------------------------------------------------------
// Fused apply with shared-memory scatter staging. Block = 16x16 pixel tile,
// 256 threads, dynamic smem box 32x32x12 (48KB), 4 blocks/SM, 64 regs.
// INIT:  s = slices[pix] - A(x)[pix]; scatter psf*s into g_r.
// ITER:  s = A(p)[pix]; scatter psf*s into g_Ap; reduce sum(s^2) = p.AtAp.
// ---------------------------------------------------------------------------
template <bool INIT>
__global__ void __launch_bounds__(APPLY_THREADS, 4) apply_kernel(
    const float* __restrict__ theta,
    const float* __restrict__ vin, const float* __restrict__ src,
    float* __restrict__ vout, double* __restrict__ dot_dst)
{
    extern __shared__ __align__(16) float sbox[];

    int b = blockIdx.x;
    int n   = b >> 6;                  // 64 tiles per slice
    int tyx = b & 63;
    int ty0 = (tyx >> 3) << 4;         // tile row * 16
    int tx0 = (tyx & 7) << 4;          // tile col * 16
    int lx = threadIdx.x & 15, ly = threadIdx.x >> 4;
    int w = tx0 + lx, h = ty0 + ly;
    int pix = (n << 14) + (h << 7) + w;

    const float* T = theta + n * 12;
    float R00 = __ldg(T + 0), R01 = __ldg(T + 1),  R02 = __ldg(T + 2),  t0 = __ldg(T + 3);
    float R10 = __ldg(T + 4), R11 = __ldg(T + 5),  R12 = __ldg(T + 6),  t1 = __ldg(T + 7);
    float R20 = __ldg(T + 8), R21 = __ldg(T + 9),  R22 = __ldg(T + 10), t2 = __ldg(T + 11);

    float u = ((float)w - 63.5f) * 1.5f;
    float v = ((float)h - 63.5f) * 1.5f;
    float cx = R00 * u + R01 * v + t0 + 63.5f;
    float cy = R10 * u + R11 * v + t1 + 63.5f;
    float cz = R20 * u + R21 * v + t2 + 63.5f;

    float a0 = fabsf(R00) + fabsf(R01) + fabsf(R02);
    float a1 = fabsf(R10) + fabsf(R11) + fabsf(R12);
    float a2 = fabsf(R20) + fabsf(R21) + fabsf(R22);

    // uniform tile bounding box of all sample points (+trilinear corner)
    float u0 = ((float)tx0 - 63.5f) * 1.5f;
    float v0 = ((float)ty0 - 63.5f) * 1.5f;
    float X00 = R00 * u0 + R01 * v0 + t0 + 63.5f;
    float Y00 = R10 * u0 + R11 * v0 + t1 + 63.5f;
    float Z00 = R20 * u0 + R21 * v0 + t2 + 63.5f;
    const float SI = 22.5f, SJ = 22.5f;    // 15*1.5 in both tile dims
    float eps = 0.01f;
    float mnx = X00 + fminf(0.f, SI * R00) + fminf(0.f, SJ * R01) - a0 - eps;
    float mxx = X00 + fmaxf(0.f, SI * R00) + fmaxf(0.f, SJ * R01) + a0 + eps;
    float mny = Y00 + fminf(0.f, SI * R10) + fminf(0.f, SJ * R11) - a1 - eps;
    float mxy = Y00 + fmaxf(0.f, SI * R10) + fmaxf(0.f, SJ * R11) + a1 + eps;
    float mnz = Z00 + fminf(0.f, SI * R20) + fminf(0.f, SJ * R21) - a2 - eps;
    float mxz = Z00 + fmaxf(0.f, SI * R20) + fmaxf(0.f, SJ * R21) + a2 + eps;
    int bx0 = (int)floorf(mnx), bx1 = (int)floorf(mxx) + 1;
    int by0 = (int)floorf(mny), by1 = (int)floorf(mxy) + 1;
    int bz0 = (int)floorf(mnz), bz1 = (int)floorf(mxz) + 1;

    if (bx1 < 0 || bx0 > Wv - 1 || by1 < 0 || by0 > Hv - 1 || bz1 < 0 || bz0 > Dv - 1)
        return;

    bool fit = (bx1 - bx0 < BX) && (by1 - by0 < BY) && (bz1 - bz0 < BZ);
    int nzp = min(bz1 - bz0 + 2, BZ);
    int ncell = nzp * (BY * BX);

    if (fit) {
        float4* s4 = (float4*)sbox;
        int n4 = ncell >> 2;
        for (int i = threadIdx.x; i < n4; i += APPLY_THREADS)
            s4[i] = make_float4(0.f, 0.f, 0.f, 0.f);
    }

    bool fully_out =
        (cx + a0 <= -1.001f) || (cx - a0 >= 128.001f) ||
        (cy + a1 <= -1.001f) || (cy - a1 >= 128.001f) ||
        (cz + a2 <= -1.001f) || (cz - a2 >= 128.001f);
    bool interior =
        (cx - a0 >= 0.001f) && (cx + a0 <= 126.999f) &&
        (cy - a1 >= 0.001f) && (cy + a1 <= 126.999f) &&
        (cz - a2 >= 0.001f) && (cz + a2 <= 126.999f);

    // ---- gather: s = A(vin) at this pixel ----
    float s = 0.f;
    if (!fully_out) {
        if (interior) {
            float sA = 0.f, sB = 0.f;   // two accumulators for ILP
            #pragma unroll
            for (int dz = 0; dz < 3; dz++) {
                float zx = cx + (float)(dz - 1) * R02;
                float zy = cy + (float)(dz - 1) * R12;
                float zz = cz + (float)(dz - 1) * R22;
                #pragma unroll
                for (int dy = 0; dy < 3; dy++) {
                    float yx = zx + (float)(dy - 1) * R01;
                    float yy = zy + (float)(dy - 1) * R11;
                    float yz = zz + (float)(dy - 1) * R21;
                    #pragma unroll
                    for (int dx = 0; dx < 3; dx++) {
                        float px = yx + (float)(dx - 1) * R00;
                        float py = yy + (float)(dx - 1) * R10;
                        float pz = yz + (float)(dx - 1) * R20;
                        float g = c_psf[(dz * 3 + dy) * 3 + dx] *
                                  trigather_fast(vin, px, py, pz);
                        if (((dz * 3 + dy) * 3 + dx) & 1) sA += g; else sB += g;
                    }
                }
            }
            s = sA + sB;
        } else {
            #pragma unroll 3
            for (int k = 0; k < 27; k++) {
                float ox = (float)(k % 3 - 1);
                float oy = (float)((k / 3) % 3 - 1);
                float oz = (float)(k / 9 - 1);
                float px = cx + ox * R00 + oy * R01 + oz * R02;
                float py = cy + ox * R10 + oy * R11 + oz * R12;
                float pz = cz + ox * R20 + oy * R21 + oz * R22;
                s += c_psf[k] * trigather_safe(vin, px, py, pz);
            }
        }
    }

    if (INIT) {
        s = __ldg(src + pix) - s;
    } else {
        block_reduce_add<8>((double)s * (double)s, dot_dst);
    }

    // ---- scatter ----
    if (fit) {
        __syncthreads();
        if (s != 0.f) {
            #pragma unroll
            for (int dz = 0; dz < 3; dz++) {
                float zx = cx + (float)(dz - 1) * R02;
                float zy = cy + (float)(dz - 1) * R12;
                float zz = cz + (float)(dz - 1) * R22;
                #pragma unroll
                for (int dy = 0; dy < 3; dy++) {
                    float yx = zx + (float)(dy - 1) * R01;
                    float yy = zy + (float)(dy - 1) * R11;
                    float yz = zz + (float)(dy - 1) * R21;
                    #pragma unroll
                    for (int dx = 0; dx < 3; dx++) {
                        float px = yx + (float)(dx - 1) * R00;
                        float py = yy + (float)(dx - 1) * R10;
                        float pz = yz + (float)(dx - 1) * R20;
                        float val = c_psf[(dz * 3 + dy) * 3 + dx] * s;
                        float xf = floorf(px), yf = floorf(py), zf = floorf(pz);
                        int ix = (int)xf - bx0, iy = (int)yf - by0, iz = (int)zf - bz0;
                        float fx = px - xf, fy = py - yf, fz = pz - zf;
                        float gx = 1.f - fx, gy = 1.f - fy, gz = 1.f - fz;
                        if ((unsigned)ix < BX - 1 && (unsigned)iy < BY - 1 &&
                            (unsigned)iz < BZ - 1) {
                            float* q = sbox + (iz * BY + iy) * BX + ix;
                            float w0 = val * gz, w1 = val * fz;
                            float gxgy = gx * gy, fxgy = fx * gy;
                            float gxfy = gx * fy, fxfy = fx * fy;
                            atomicAdd(q,              gxgy * w0);
                            atomicAdd(q + 1,          fxgy * w0);
                            atomicAdd(q + BX,         gxfy * w0);
                            atomicAdd(q + BX + 1,     fxfy * w0);
                            float* q2 = q + BY * BX;
                            atomicAdd(q2,             gxgy * w1);
                            atomicAdd(q2 + 1,         fxgy * w1);
                            atomicAdd(q2 + BX,        gxfy * w1);
                            atomicAdd(q2 + BX + 1,    fxfy * w1);
                        } else {
                            triscatter_safe(vout, px, py, pz, val);
                        }
                    }
                }
            }
        }
        __syncthreads();
        // clipped flush over active cells only
        for (int i = threadIdx.x; i < ncell; i += APPLY_THREADS) {
            float val = sbox[i];
            if (val != 0.f) {
                int gx = bx0 + (i & (BX - 1));
                int gy = by0 + ((i >> 5) & (BY - 1));
                int gz = bz0 + (i >> 10);
                if ((unsigned)gx < (unsigned)Wv && (unsigned)gy < (unsigned)Hv &&
                    (unsigned)gz < (unsigned)Dv)
                    atomicAdd(vout + ((gz * Hv + gy) << 7) + gx, val);
            }
        }
    } else if (!fully_out && s != 0.f) {
        #pragma unroll 3
        for (int k = 0; k < 27; k++) {
            float ox = (float)(k % 3 - 1);
            float oy = (float)((k / 3) % 3 - 1);
            float oz = (float)(k / 9 - 1);
            float px = cx + ox * R00 + oy * R01 + oz * R02;
            float py = cy + ox * R10 + oy * R11 + oz * R12;
            float pz = cz + ox * R20 + oy * R21 + oz * R22;
            triscatter_safe(vout, px, py, pz, c_psf[k] * s);
        }
    }
}

// ---------------------------------------------------------------------------
// Vectorized CG plumbing: float4, 512 blocks x 256 threads, fixed 4-iter unroll.
// ---------------------------------------------------------------------------
#define VGRID 512
#define VTHREADS 256
#define VSTRIDE (VGRID * VTHREADS)

__global__ void __launch_bounds__(VTHREADS) setup_kernel(const float4* __restrict__ vol) {
    int i = blockIdx.x * VTHREADS + threadIdx.x;
    float4 z = make_float4(0.f, 0.f, 0.f, 0.f);
    float4* r4 = (float4*)g_r;
    float4* x4 = (float4*)g_x;
    #pragma unroll
    for (int k = 0; k < 4; k++) {
        int j = i + k * VSTRIDE;
        r4[j] = z;
        x4[j] = vol[j];
    }
    if (i < NIT + 1) g_rr[i] = 0.0;
    if (i >= 64 && i < 64 + NIT) g_pAp[i - 64] = 0.0;
}

__global__ void __launch_bounds__(VTHREADS) init_r_kernel() {
    int i = blockIdx.x * VTHREADS + threadIdx.x;
    const float4* r4 = (const float4*)g_r;
    float4* p4  = (float4*)g_p;
    float4* ap4 = (float4*)g_Ap;
    float4 z = make_float4(0.f, 0.f, 0.f, 0.f);
    double acc = 0.0;
    #pragma unroll
    for (int k = 0; k < 4; k++) {
        int j = i + k * VSTRIDE;
        float4 rv = r4[j];
        p4[j] = rv;
        ap4[j] = z;
        acc += (double)rv.x * rv.x + (double)rv.y * rv.y +
               (double)rv.z * rv.z + (double)rv.w * rv.w;
    }
    block_reduce_add<8>(acc, &g_rr[0]);
}

// Fused update: phase1 (x,r,rr reduce) -> grid barrier -> phase2 (beta, p, Ap=0)
__global__ void __launch_bounds__(VTHREADS) fused_update_kernel(int it) {
    __shared__ float s_alpha;
    if (threadIdx.x == 0) s_alpha = (float)(g_rr[it] / g_pAp[it]);
    __syncthreads();
    float alpha = s_alpha;
    int i = blockIdx.x * VTHREADS + threadIdx.x;
    float4* x4  = (float4*)g_x;
    float4* r4  = (float4*)g_r;
    float4* p4  = (float4*)g_p;
    float4* ap4 = (float4*)g_Ap;
    double acc = 0.0;
    float4 rloc[4];
    #pragma unroll
    for (int k = 0; k < 4; k++) {
        int j = i + k * VSTRIDE;
        float4 x = x4[j], p = p4[j], r = r4[j], a = ap4[j];
        x.x += alpha * p.x; x.y += alpha * p.y; x.z += alpha * p.z; x.w += alpha * p.w;
        r.x -= alpha * a.x; r.y -= alpha * a.y; r.z -= alpha * a.z; r.w -= alpha * a.w;
        x4[j] = x;
        r4[j] = r;
        rloc[k] = r;
        acc += (double)r.x * r.x + (double)r.y * r.y +
               (double)r.z * r.z + (double)r.w * r.w;
    }
    block_reduce_add<8>(acc, &g_rr[it + 1]);

    grid_barrier(VGRID);

    __shared__ float s_beta;
    if (threadIdx.x == 0) {
        double rrn = *(volatile double*)&g_rr[it + 1];
        s_beta = (float)(rrn / g_rr[it]);
    }
    __syncthreads();
    float beta = s_beta;
    float4 z = make_float4(0.f, 0.f, 0.f, 0.f);
    #pragma unroll
    for (int k = 0; k < 4; k++) {
        int j = i + k * VSTRIDE;
        float4 r = rloc[k], p = p4[j];
        p.x = r.x + beta * p.x; p.y = r.y + beta * p.y;
        p.z = r.z + beta * p.z; p.w = r.w + beta * p.w;
        p4[j] = p;
        ap4[j] = z;
    }
}

__global__ void __launch_bounds__(VTHREADS) final_kernel(float4* __restrict__ out) {
    __shared__ float s_alpha;
    if (threadIdx.x == 0) s_alpha = (float)(g_rr[NIT - 1] / g_pAp[NIT - 1]);
    __syncthreads();
    float alpha = s_alpha;
    int i = blockIdx.x * VTHREADS + threadIdx.x;
    const float4* x4 = (const float4*)g_x;
    const float4* p4 = (const float4*)g_p;
    #pragma unroll
    for (int k = 0; k < 4; k++) {
        int j = i + k * VSTRIDE;
        float4 x = x4[j], p = p4[j];
        out[j] = make_float4(fmaxf(x.x + alpha * p.x, 0.f),
                             fmaxf(x.y + alpha * p.y, 0.f),
                             fmaxf(x.z + alpha * p.z, 0.f),
                             fmaxf(x.w + alpha * p.w, 0.f));
    }
}

// ---------------------------------------------------------------------------
// Launch
// ---------------------------------------------------------------------------
extern "C" void kernel_launch(void* const* d_in, const int* in_sizes, int n_in,
                              void* d_out, int out_size) {
    const float *theta = nullptr, *slices = nullptr, *volume = nullptr, *psf = nullptr;
    for (int i = 0; i < n_in; i++) {
        switch (in_sizes[i]) {
            case 192:     theta  = (const float*)d_in[i]; break;
            case 262144:  slices = (const float*)d_in[i]; break;
            case 2097152: volume = (const float*)d_in[i]; break;
            case 27:      psf    = (const float*)d_in[i]; break;
        }
    }

    const int SBYTES = BVOL * (int)sizeof(float);   // 49152

    static float* pr  = nullptr;
    static float* pp  = nullptr;
    static float* px_ = nullptr;
    static float* pAp = nullptr;
    static double* ppAp = nullptr;
    if (!pr) {
        cudaGetSymbolAddress((void**)&pr,   g_r);
        cudaGetSymbolAddress((void**)&pp,   g_p);
        cudaGetSymbolAddress((void**)&px_,  g_x);
        cudaGetSymbolAddress((void**)&pAp,  g_Ap);
        cudaGetSymbolAddress((void**)&ppAp, g_pAp);
        cudaFuncSetAttribute(apply_kernel<true>,
                             cudaFuncAttributeMaxDynamicSharedMemorySize, SBYTES);
        cudaFuncSetAttribute(apply_kernel<false>,
                             cudaFuncAttributeMaxDynamicSharedMemorySize, SBYTES);
    }

    const int PB = NPIX / 256;   // 1024 tile blocks (16x16 tiles)

    // psf -> constant memory (D2D async copy; graph-capturable)
    cudaMemcpyToSymbolAsync(c_psf, psf, 27 * sizeof(float), 0,
                            cudaMemcpyDeviceToDevice, 0);

    setup_kernel<<<VGRID, VTHREADS>>>((const float4*)volume);
    // r0 = At(slices - A x0), scattered directly into g_r
    apply_kernel<true><<<PB, APPLY_THREADS, SBYTES>>>(theta, px_, slices, pr, nullptr);
    // p = r; Ap = 0; rr0
    init_r_kernel<<<VGRID, VTHREADS>>>();

    for (int it = 0; it < NIT; it++) {
        // Ap = AtA(p); pAp = sum(s^2)
        apply_kernel<false><<<PB, APPLY_THREADS, SBYTES>>>(theta, pp, nullptr, pAp, ppAp + it);
        if (it == NIT - 1) {
            final_kernel<<<VGRID, VTHREADS>>>((float4*)d_out);
        } else {
            fused_update_kernel<<<VGRID, VTHREADS>>>(it);
        }
    }
}